// round 5
// baseline (speedup 1.0000x reference)
#include <cuda_runtime.h>
#include <cstdint>

// Problem constants
#define BATCH 2
#define SEQ   2048
#define DMODEL 1024
#define NHEADS 16
#define DK    64
#define BL    (BATCH*SEQ)          // 4096 rows

// Scratch: Q/K/V in [b,h,l,k] layout, ctx in [b,l,h*dk]
__device__ __align__(16) float g_Q[BATCH*NHEADS*SEQ*DK];
__device__ __align__(16) float g_K[BATCH*NHEADS*SEQ*DK];
__device__ __align__(16) float g_V[BATCH*NHEADS*SEQ*DK];
__device__ __align__(16) float g_ctx[BATCH*SEQ*DMODEL];

// ---------------------------------------------------------------------------
// f32x2 packed helpers (PTX ISA 8.6+, sm_100 family; arch-agnostic, no 'a')
// ---------------------------------------------------------------------------
__device__ __forceinline__ uint64_t pack2(float x, float y) {
    uint64_t r;
    asm("mov.b64 %0, {%1, %2};" : "=l"(r) : "f"(x), "f"(y));
    return r;
}
__device__ __forceinline__ uint64_t pack2v(float2 v) { return pack2(v.x, v.y); }
__device__ __forceinline__ void unpack2(uint64_t v, float& x, float& y) {
    asm("mov.b64 {%0, %1}, %2;" : "=f"(x), "=f"(y) : "l"(v));
}
__device__ __forceinline__ float fold2(uint64_t v) {
    float x, y;
    unpack2(v, x, y);
    return x + y;
}
__device__ __forceinline__ void fma2(uint64_t& d, uint64_t a, uint64_t b) {
    asm("fma.rn.f32x2 %0, %1, %2, %0;" : "+l"(d) : "l"(a), "l"(b));
}
__device__ __forceinline__ void mul2(uint64_t& d, uint64_t a) {
    asm("mul.rn.f32x2 %0, %0, %1;" : "+l"(d) : "l"(a));
}

// ---------------------------------------------------------------------------
// Shared GEMM inner compute: one BK=16 stage over a 128x128 tile.
// As[k][m] (k-transposed, stride 128), Bs[k][n] (stride 128).
// Thread (ty,tx) owns rows ty*8..ty*8+7 (as 4 m-pairs) and cols
// tx*2 + {0,1} + 32*{0..3}.  acc2[i][j] = outputs (row 2i, row 2i+1, col j).
// ---------------------------------------------------------------------------
__device__ __forceinline__ void gemm_stage(const float* __restrict__ As,
                                           const float* __restrict__ Bs,
                                           uint64_t acc2[4][8],
                                           int ty, int tx)
{
    #pragma unroll
    for (int k = 0; k < 16; ++k) {
        const float* ar = As + k * 128 + ty * 8;
        const float* br = Bs + k * 128 + tx * 2;
        uint64_t a2[4];
        #pragma unroll
        for (int i = 0; i < 4; ++i)
            a2[i] = pack2v(*(const float2*)(ar + 2 * i));   // aligned LDS.64
        uint64_t b2[8];
        #pragma unroll
        for (int j = 0; j < 8; ++j) {
            const float bv = br[(j & 1) + 32 * (j >> 1)];
            b2[j] = pack2(bv, bv);
        }
        #pragma unroll
        for (int i = 0; i < 4; ++i)
            #pragma unroll
            for (int j = 0; j < 8; ++j)
                fma2(acc2[i][j], a2[i], b2[j]);
    }
}

// ---------------------------------------------------------------------------
// Kernel 1: fused QKV projection, f32x2.
//   C[b,h,l,kc] = sum_d A[b,l,d] * W[h,d,kc]
// M=4096, N=1024 (h*64+kc), K=1024.  B read in natural [d][kc] layout.
// grid (8 n-tiles, 32 m-tiles, 3 which), 256 threads.
// ---------------------------------------------------------------------------
__global__ __launch_bounds__(256)
void gemm_qkv_kernel(const float* __restrict__ q,
                     const float* __restrict__ k,
                     const float* __restrict__ v,
                     const float* __restrict__ wq,
                     const float* __restrict__ wk,
                     const float* __restrict__ wv)
{
    __shared__ __align__(16) float As[2][16 * 128];
    __shared__ __align__(16) float Bs[2][16 * 128];

    const int tid = threadIdx.x;
    const int tx = tid & 15, ty = tid >> 4;
    const int which = blockIdx.z;
    const float* A = (which == 0) ? q : (which == 1) ? k : v;
    const float* W = (which == 0) ? wq : (which == 1) ? wk : wv;
    float* C = (which == 0) ? g_Q : (which == 1) ? g_K : g_V;
    const int m0 = blockIdx.y * 128, n0 = blockIdx.x * 128;

    // A loader coords: 4 float2 per stage
    const int arow = tid >> 3;            // 0..31 (+32 per l)
    const int ap   = (tid & 7) * 2;       // k offset within stage
    // B loader coords: 2 float4 per stage
    const int bk   = tid >> 5;            // 0..7 (+8 per l)
    const int bc4  = tid & 31;            // col/4
    const int hsel = (n0 >> 6) + (bc4 >> 4);
    const int bcol = (bc4 & 15) * 4;
    const float* Wb = W + (size_t)hsel * DMODEL * DK + bcol;

    uint64_t acc2[4][8];
    #pragma unroll
    for (int i = 0; i < 4; ++i)
        #pragma unroll
        for (int j = 0; j < 8; ++j) acc2[i][j] = 0ull;

    float2 pa[4];
    float4 pb[2];
    #pragma unroll
    for (int l = 0; l < 4; ++l)
        pa[l] = *(const float2*)(A + (size_t)(m0 + arow + 32 * l) * DMODEL + ap);
    #pragma unroll
    for (int l = 0; l < 2; ++l)
        pb[l] = *(const float4*)(Wb + (size_t)(bk + 8 * l) * DK);
    #pragma unroll
    for (int l = 0; l < 4; ++l) {
        As[0][ap * 128 + arow + 32 * l]       = pa[l].x;
        As[0][(ap + 1) * 128 + arow + 32 * l] = pa[l].y;
    }
    #pragma unroll
    for (int l = 0; l < 2; ++l)
        *(float4*)&Bs[0][(bk + 8 * l) * 128 + bc4 * 4] = pb[l];
    __syncthreads();

    for (int s = 0; s < 64; ++s) {
        const int buf = s & 1;
        if (s < 63) {
            const int k0 = (s + 1) * 16;
            #pragma unroll
            for (int l = 0; l < 4; ++l)
                pa[l] = *(const float2*)(A + (size_t)(m0 + arow + 32 * l) * DMODEL + k0 + ap);
            #pragma unroll
            for (int l = 0; l < 2; ++l)
                pb[l] = *(const float4*)(Wb + (size_t)(k0 + bk + 8 * l) * DK);
        }
        gemm_stage(As[buf], Bs[buf], acc2, ty, tx);
        if (s < 63) {
            #pragma unroll
            for (int l = 0; l < 4; ++l) {
                As[buf ^ 1][ap * 128 + arow + 32 * l]       = pa[l].x;
                As[buf ^ 1][(ap + 1) * 128 + arow + 32 * l] = pa[l].y;
            }
            #pragma unroll
            for (int l = 0; l < 2; ++l)
                *(float4*)&Bs[buf ^ 1][(bk + 8 * l) * 128 + bc4 * 4] = pb[l];
        }
        __syncthreads();
    }

    // epilogue: write to [b,h,l,kc]
    #pragma unroll
    for (int i = 0; i < 4; ++i) {
        const int r0 = m0 + ty * 8 + 2 * i;
        const int b0i = r0 >> 11, l0i = r0 & 2047;
        const int b1i = (r0 + 1) >> 11, l1i = (r0 + 1) & 2047;
        #pragma unroll
        for (int j = 0; j < 8; ++j) {
            const int col = n0 + tx * 2 + (j & 1) + 32 * (j >> 1);
            const int h = col >> 6, kc = col & 63;
            float lo, hi;
            unpack2(acc2[i][j], lo, hi);
            C[(((size_t)(b0i * NHEADS + h) * SEQ) + l0i) * DK + kc] = lo;
            C[(((size_t)(b1i * NHEADS + h) * SEQ) + l1i) * DK + kc] = hi;
        }
    }
}

// ---------------------------------------------------------------------------
// Kernel 3: output projection, f32x2.  out = ctx @ out_w + out_b
// M=4096, N=1024, K=1024.  grid (8, 32), 256 threads.
// ---------------------------------------------------------------------------
__global__ __launch_bounds__(256)
void gemm_out_kernel(const float* __restrict__ out_w,
                     const float* __restrict__ out_b,
                     float* __restrict__ out)
{
    __shared__ __align__(16) float As[2][16 * 128];
    __shared__ __align__(16) float Bs[2][16 * 128];

    const int tid = threadIdx.x;
    const int tx = tid & 15, ty = tid >> 4;
    const int m0 = blockIdx.y * 128, n0 = blockIdx.x * 128;

    const int arow = tid >> 3;
    const int ap   = (tid & 7) * 2;
    const int bk   = tid >> 5;
    const int bc4  = tid & 31;
    const float* Bg = out_w + n0 + bc4 * 4;

    uint64_t acc2[4][8];
    #pragma unroll
    for (int i = 0; i < 4; ++i)
        #pragma unroll
        for (int j = 0; j < 8; ++j) acc2[i][j] = 0ull;

    float2 pa[4];
    float4 pb[2];
    #pragma unroll
    for (int l = 0; l < 4; ++l)
        pa[l] = *(const float2*)(g_ctx + (size_t)(m0 + arow + 32 * l) * DMODEL + ap);
    #pragma unroll
    for (int l = 0; l < 2; ++l)
        pb[l] = *(const float4*)(Bg + (size_t)(bk + 8 * l) * DMODEL);
    #pragma unroll
    for (int l = 0; l < 4; ++l) {
        As[0][ap * 128 + arow + 32 * l]       = pa[l].x;
        As[0][(ap + 1) * 128 + arow + 32 * l] = pa[l].y;
    }
    #pragma unroll
    for (int l = 0; l < 2; ++l)
        *(float4*)&Bs[0][(bk + 8 * l) * 128 + bc4 * 4] = pb[l];
    __syncthreads();

    for (int s = 0; s < 64; ++s) {
        const int buf = s & 1;
        if (s < 63) {
            const int k0 = (s + 1) * 16;
            #pragma unroll
            for (int l = 0; l < 4; ++l)
                pa[l] = *(const float2*)(g_ctx + (size_t)(m0 + arow + 32 * l) * DMODEL + k0 + ap);
            #pragma unroll
            for (int l = 0; l < 2; ++l)
                pb[l] = *(const float4*)(Bg + (size_t)(k0 + bk + 8 * l) * DMODEL);
        }
        gemm_stage(As[buf], Bs[buf], acc2, ty, tx);
        if (s < 63) {
            #pragma unroll
            for (int l = 0; l < 4; ++l) {
                As[buf ^ 1][ap * 128 + arow + 32 * l]       = pa[l].x;
                As[buf ^ 1][(ap + 1) * 128 + arow + 32 * l] = pa[l].y;
            }
            #pragma unroll
            for (int l = 0; l < 2; ++l)
                *(float4*)&Bs[buf ^ 1][(bk + 8 * l) * 128 + bc4 * 4] = pb[l];
        }
        __syncthreads();
    }

    #pragma unroll
    for (int i = 0; i < 4; ++i) {
        const int r0 = m0 + ty * 8 + 2 * i;
        #pragma unroll
        for (int j = 0; j < 8; ++j) {
            const int col = n0 + tx * 2 + (j & 1) + 32 * (j >> 1);
            float lo, hi;
            unpack2(acc2[i][j], lo, hi);
            const float bb = out_b[col];
            out[(size_t)r0 * DMODEL + col]       = lo + bb;
            out[(size_t)(r0 + 1) * DMODEL + col] = hi + bb;
        }
    }
}

// ---------------------------------------------------------------------------
// Kernel 2: flash attention with f32x2 packed FFMA (pairs along k).
// Qs/Ps/Vt use even stride 66 (8B-aligned rows); Ks stride 65 (scalar loads).
// Phase bias is constant along the softmax axis -> cancels exactly.
// ---------------------------------------------------------------------------
#define SAQ 66
#define SAK 65
#define SAV 66

__global__ __launch_bounds__(256)
void attn_kernel()
{
    extern __shared__ float smf[];
    float* Qs = smf;                       // [64][66]
    float* Ks = Qs + 64 * SAQ;             // [64][65]
    float* Vt = Ks + 64 * SAK;             // [64][66]  Vt[c][k] = V[k][c]
    float* Ps = Vt + 64 * SAV;             // [64][66]

    const int tid = threadIdx.x;
    const int tx = tid & 15, ty = tid >> 4;
    const int qt = blockIdx.x;
    const int bhid = blockIdx.y;

    const float* Qg = g_Q + (size_t)bhid * SEQ * DK + (size_t)qt * 64 * DK;
    const float* Kg = g_K + (size_t)bhid * SEQ * DK;
    const float* Vg = g_V + (size_t)bhid * SEQ * DK;

    for (int i = tid; i < 64 * DK; i += 256)
        Qs[(i >> 6) * SAQ + (i & 63)] = Qg[i] * 0.125f;

    uint64_t acc2[4][4];
    #pragma unroll
    for (int i = 0; i < 4; ++i)
        #pragma unroll
        for (int j = 0; j < 4; ++j) acc2[i][j] = 0ull;
    float mrow[4], lrow[4];
    #pragma unroll
    for (int i = 0; i < 4; ++i) { mrow[i] = -1e30f; lrow[i] = 0.f; }

    __syncthreads();

    const float* QsA = Qs + (ty * 4) * SAQ;
    const float* PsA = Ps + (ty * 4) * SAQ;
    const float* KsB = Ks + (tx * 4) * SAK;
    const float* VtB = Vt + (tx * 4) * SAV;

    for (int kt = 0; kt < SEQ / 64; ++kt) {
        const float* kp = Kg + (size_t)kt * 64 * DK;
        const float* vp = Vg + (size_t)kt * 64 * DK;
        for (int i = tid; i < 64 * DK; i += 256) {
            const int r = i >> 6, c = i & 63;
            Ks[r * SAK + c] = kp[i];
            Vt[c * SAV + r] = vp[i];
        }
        __syncthreads();

        // S = Q K^T  (packed along k)
        uint64_t s2[4][4];
        #pragma unroll
        for (int i = 0; i < 4; ++i)
            #pragma unroll
            for (int j = 0; j < 4; ++j) s2[i][j] = 0ull;

        #pragma unroll 4
        for (int k = 0; k < DK; k += 2) {
            uint64_t a2[4], b2[4];
            #pragma unroll
            for (int i = 0; i < 4; ++i)
                a2[i] = pack2v(*(const float2*)(QsA + i * SAQ + k));
            #pragma unroll
            for (int j = 0; j < 4; ++j)
                b2[j] = pack2(KsB[j * SAK + k], KsB[j * SAK + k + 1]);
            #pragma unroll
            for (int i = 0; i < 4; ++i)
                #pragma unroll
                for (int j = 0; j < 4; ++j)
                    fma2(s2[i][j], a2[i], b2[j]);
        }

        // online softmax update per row
        #pragma unroll
        for (int i = 0; i < 4; ++i) {
            float s[4];
            #pragma unroll
            for (int j = 0; j < 4; ++j) s[j] = fold2(s2[i][j]);
            float lm = fmaxf(fmaxf(s[0], s[1]), fmaxf(s[2], s[3]));
            #pragma unroll
            for (int off = 8; off > 0; off >>= 1)
                lm = fmaxf(lm, __shfl_xor_sync(0xffffffffu, lm, off));
            const float Mn = fmaxf(mrow[i], lm);
            const float corr = __expf(mrow[i] - Mn);
            float rs = 0.f;
            #pragma unroll
            for (int j = 0; j < 4; ++j) {
                s[j] = __expf(s[j] - Mn);
                rs += s[j];
            }
            #pragma unroll
            for (int off = 8; off > 0; off >>= 1)
                rs += __shfl_xor_sync(0xffffffffu, rs, off);
            lrow[i] = lrow[i] * corr + rs;
            mrow[i] = Mn;
            const uint64_t c2 = pack2(corr, corr);
            #pragma unroll
            for (int j = 0; j < 4; ++j) mul2(acc2[i][j], c2);
            #pragma unroll
            for (int j = 0; j < 4; ++j)
                Ps[(ty * 4 + i) * SAQ + tx * 4 + j] = s[j];
        }
        __syncthreads();

        // O += P V  (packed along k; both operands contiguous in k)
        #pragma unroll 4
        for (int k = 0; k < 64; k += 2) {
            uint64_t a2[4], b2[4];
            #pragma unroll
            for (int i = 0; i < 4; ++i)
                a2[i] = pack2v(*(const float2*)(PsA + i * SAQ + k));
            #pragma unroll
            for (int j = 0; j < 4; ++j)
                b2[j] = pack2v(*(const float2*)(VtB + j * SAV + k));
            #pragma unroll
            for (int i = 0; i < 4; ++i)
                #pragma unroll
                for (int j = 0; j < 4; ++j)
                    fma2(acc2[i][j], a2[i], b2[j]);
        }
        __syncthreads();
    }

    const int b = bhid >> 4, h = bhid & 15;
    const int l0 = qt * 64;
    #pragma unroll
    for (int i = 0; i < 4; ++i) {
        const float inv = 1.0f / lrow[i];
        float* cp = g_ctx + ((size_t)(b * SEQ + l0 + ty * 4 + i)) * DMODEL
                    + h * DK + tx * 4;
        #pragma unroll
        for (int j = 0; j < 4; ++j) cp[j] = fold2(acc2[i][j]) * inv;
    }
}

// ---------------------------------------------------------------------------
// Launch.  Inputs: query, key, value, Wq, Wk, Wv, out_w, out_b, coupling
// coupling is (correctly) unused: the Kuramoto phase bias is constant along
// the softmax axis and cancels exactly.
// ---------------------------------------------------------------------------
extern "C" void kernel_launch(void* const* d_in, const int* in_sizes, int n_in,
                              void* d_out, int out_size)
{
    const float* q     = (const float*)d_in[0];
    const float* k     = (const float*)d_in[1];
    const float* v     = (const float*)d_in[2];
    const float* wq    = (const float*)d_in[3];
    const float* wk    = (const float*)d_in[4];
    const float* wv    = (const float*)d_in[5];
    const float* out_w = (const float*)d_in[6];
    const float* out_b = (const float*)d_in[7];
    float* out = (float*)d_out;

    // QKV projection (f32x2): 8 n-tiles x 32 m-tiles x {Q,K,V}
    gemm_qkv_kernel<<<dim3(8, 32, 3), 256>>>(q, k, v, wq, wk, wv);

    // attention (f32x2): 32 q-tiles x 32 (b,h)
    const int smem = (SAQ + SAK + SAV + SAQ) * 64 * sizeof(float);  // 67328
    cudaFuncSetAttribute(attn_kernel,
                         cudaFuncAttributeMaxDynamicSharedMemorySize, smem);
    attn_kernel<<<dim3(SEQ / 64, BATCH * NHEADS), 256, smem>>>();

    // output projection (f32x2)
    gemm_out_kernel<<<dim3(8, 32), 256>>>(out_w, out_b, out);
}

// round 8
// speedup vs baseline: 1.5425x; 1.5425x over previous
#include <cuda_runtime.h>
#include <cuda_bf16.h>
#include <cstdint>

// Problem constants
#define BATCH 2
#define SEQ   2048
#define DMODEL 1024
#define NHEADS 16
#define DK    64
#define BL    (BATCH*SEQ)          // 4096 rows

// fp32 scratch
__device__ __align__(16) float g_Q[BATCH*NHEADS*SEQ*DK];
__device__ __align__(16) float g_K[BATCH*NHEADS*SEQ*DK];
__device__ __align__(16) float g_V[BATCH*NHEADS*SEQ*DK];
__device__ __align__(16) float g_ctx[BATCH*SEQ*DMODEL];

// bf16 split operands (ver 0 = hi, ver 1 = lo)
__device__ __align__(16) __nv_bfloat16 g_Abf[3][2][BL*DMODEL];      // q/k/v acts
__device__ __align__(16) __nv_bfloat16 g_Wbf[3][2][DMODEL*DMODEL];  // W packed [d][h*64+kc]
__device__ __align__(16) __nv_bfloat16 g_Wobf[2][DMODEL*DMODEL];    // out_w [d][n]
__device__ __align__(16) __nv_bfloat16 g_Cbf[2][BL*DMODEL];         // ctx

// ---------------------------------------------------------------------------
// PTX helpers (all plain sm_80-class; no arch-specific 'a' features)
// ---------------------------------------------------------------------------
__device__ __forceinline__ uint32_t smem_u32(const void* p) {
    uint32_t a;
    asm("{ .reg .u64 t; cvta.to.shared.u64 t, %1; cvt.u32.u64 %0, t; }"
        : "=r"(a) : "l"(p));
    return a;
}
#define CP16(s, g) \
    asm volatile("cp.async.cg.shared.global [%0], [%1], 16;" :: "r"(s), "l"(g) : "memory")
#define CP_COMMIT() asm volatile("cp.async.commit_group;" ::: "memory")

__device__ __forceinline__ void ldmA(uint32_t r[4], uint32_t addr) {
    asm volatile("ldmatrix.sync.aligned.m8n8.x4.shared.b16 {%0,%1,%2,%3}, [%4];"
                 : "=r"(r[0]), "=r"(r[1]), "=r"(r[2]), "=r"(r[3]) : "r"(addr));
}
__device__ __forceinline__ void ldmBT(uint32_t r[4], uint32_t addr) {
    asm volatile("ldmatrix.sync.aligned.m8n8.x4.trans.shared.b16 {%0,%1,%2,%3}, [%4];"
                 : "=r"(r[0]), "=r"(r[1]), "=r"(r[2]), "=r"(r[3]) : "r"(addr));
}
__device__ __forceinline__ void mma_bf16(float c[4], const uint32_t a[4],
                                         const uint32_t b[2]) {
    asm volatile("mma.sync.aligned.m16n8k16.row.col.f32.bf16.bf16.f32 "
                 "{%0,%1,%2,%3}, {%4,%5,%6,%7}, {%8,%9}, {%0,%1,%2,%3};"
                 : "+f"(c[0]), "+f"(c[1]), "+f"(c[2]), "+f"(c[3])
                 : "r"(a[0]), "r"(a[1]), "r"(a[2]), "r"(a[3]),
                   "r"(b[0]), "r"(b[1]));
}

// ---------------------------------------------------------------------------
// bf16 hi/lo split conversions
// ---------------------------------------------------------------------------
__device__ __forceinline__ void split1(float x, __nv_bfloat16& h, __nv_bfloat16& l) {
    h = __float2bfloat16(x);
    l = __float2bfloat16(x - __bfloat162float(h));
}

__global__ void convert_act_kernel(const float* __restrict__ q,
                                   const float* __restrict__ k,
                                   const float* __restrict__ v)
{
    const int which = blockIdx.y;
    const float4* src = (const float4*)(which == 0 ? q : which == 1 ? k : v);
    __nv_bfloat16* hi = g_Abf[which][0];
    __nv_bfloat16* lo = g_Abf[which][1];
    const int n4 = BL * DMODEL / 4;
    for (int i = blockIdx.x * blockDim.x + threadIdx.x; i < n4;
         i += gridDim.x * blockDim.x) {
        float4 x = src[i];
        __nv_bfloat16 h, l;
        split1(x.x, h, l); hi[4*i+0] = h; lo[4*i+0] = l;
        split1(x.y, h, l); hi[4*i+1] = h; lo[4*i+1] = l;
        split1(x.z, h, l); hi[4*i+2] = h; lo[4*i+2] = l;
        split1(x.w, h, l); hi[4*i+3] = h; lo[4*i+3] = l;
    }
}

// W[h][d][kc] -> g_Wbf[which][ver][d*1024 + h*64 + kc]
__global__ void convert_w_kernel(const float* __restrict__ wq,
                                 const float* __restrict__ wk,
                                 const float* __restrict__ wv)
{
    const int which = blockIdx.y;
    const float4* src = (const float4*)(which == 0 ? wq : which == 1 ? wk : wv);
    const int n4 = DMODEL * DMODEL / 4;
    for (int i = blockIdx.x * blockDim.x + threadIdx.x; i < n4;
         i += gridDim.x * blockDim.x) {
        const int flat = i * 4;
        const int h = flat >> 16, d = (flat >> 6) & 1023, kc = flat & 63;
        const int dst = d * DMODEL + h * 64 + kc;
        float4 x = src[i];
        __nv_bfloat16 hh, ll;
        split1(x.x, hh, ll); g_Wbf[which][0][dst+0] = hh; g_Wbf[which][1][dst+0] = ll;
        split1(x.y, hh, ll); g_Wbf[which][0][dst+1] = hh; g_Wbf[which][1][dst+1] = ll;
        split1(x.z, hh, ll); g_Wbf[which][0][dst+2] = hh; g_Wbf[which][1][dst+2] = ll;
        split1(x.w, hh, ll); g_Wbf[which][0][dst+3] = hh; g_Wbf[which][1][dst+3] = ll;
    }
}

__global__ void convert_outw_kernel(const float* __restrict__ src4f)
{
    const float4* src = (const float4*)src4f;
    const int n4 = DMODEL * DMODEL / 4;
    for (int i = blockIdx.x * blockDim.x + threadIdx.x; i < n4;
         i += gridDim.x * blockDim.x) {
        float4 x = src[i];
        __nv_bfloat16 h, l;
        split1(x.x, h, l); g_Wobf[0][4*i+0] = h; g_Wobf[1][4*i+0] = l;
        split1(x.y, h, l); g_Wobf[0][4*i+1] = h; g_Wobf[1][4*i+1] = l;
        split1(x.z, h, l); g_Wobf[0][4*i+2] = h; g_Wobf[1][4*i+2] = l;
        split1(x.w, h, l); g_Wobf[0][4*i+3] = h; g_Wobf[1][4*i+3] = l;
    }
}

__global__ void convert_ctx_kernel()
{
    const float4* src = (const float4*)g_ctx;
    const int n4 = BL * DMODEL / 4;
    for (int i = blockIdx.x * blockDim.x + threadIdx.x; i < n4;
         i += gridDim.x * blockDim.x) {
        float4 x = src[i];
        __nv_bfloat16 h, l;
        split1(x.x, h, l); g_Cbf[0][4*i+0] = h; g_Cbf[1][4*i+0] = l;
        split1(x.y, h, l); g_Cbf[0][4*i+1] = h; g_Cbf[1][4*i+1] = l;
        split1(x.z, h, l); g_Cbf[0][4*i+2] = h; g_Cbf[1][4*i+2] = l;
        split1(x.w, h, l); g_Cbf[0][4*i+3] = h; g_Cbf[1][4*i+3] = l;
    }
}

// ---------------------------------------------------------------------------
// bf16-split GEMM: C[128x128 tile] = (Ahi+Alo)(Bhi+Blo), dropping lo*lo.
// A bf16 [m][k] row-major, B bf16 [k][n] row-major.  BK=32, double buffered.
// SMEM: A[buf][ver]: 128 rows x 32 bf16, row stride 80B.  B[buf][ver]: 32 rows
// x 128 bf16, row stride 272B.  Strides chosen conflict-free for ldmatrix.
// 8 warps as 2(m) x 4(n); warp tile 64x32 -> 4 m-frags x 4 n-frags.
// ---------------------------------------------------------------------------
#define SM_A(buf, ver) ((buf) * 20480 + (ver) * 10240)
#define SM_B(buf, ver) (40960 + (buf) * 17408 + (ver) * 8704)
#define GSMEM 75776

__device__ __forceinline__ void gemm_load_stage(
    uint32_t smb, int buf,
    const __nv_bfloat16* __restrict__ gAhi, const __nv_bfloat16* __restrict__ gAlo,
    const __nv_bfloat16* __restrict__ gBhi, const __nv_bfloat16* __restrict__ gBlo,
    int m0, int n0, int k0, int tid)
{
    #pragma unroll
    for (int j = 0; j < 4; ++j) {
        const int idx = tid + 256 * j;
        const int ver = idx >> 9, r = idx & 511;
        const int row = r >> 2, c16 = r & 3;
        const __nv_bfloat16* src = (ver ? gAlo : gAhi)
            + (size_t)(m0 + row) * DMODEL + k0 + c16 * 8;
        CP16(smb + SM_A(buf, ver) + row * 80 + c16 * 16, src);
    }
    #pragma unroll
    for (int j = 0; j < 4; ++j) {
        const int idx = tid + 256 * j;
        const int ver = idx >> 9, r = idx & 511;
        const int krow = r >> 4, c16 = r & 15;
        const __nv_bfloat16* src = (ver ? gBlo : gBhi)
            + (size_t)(k0 + krow) * DMODEL + n0 + c16 * 8;
        CP16(smb + SM_B(buf, ver) + krow * 272 + c16 * 16, src);
    }
    CP_COMMIT();
}

__device__ __forceinline__ void gemm_compute_stage(
    uint32_t smb, int buf, float acc[4][4][4], int wm, int wn, int lane)
{
    const int rowA = (lane & 7) + ((lane >> 3) & 1) * 8;
    const int kcA  = (lane >> 4) * 8;
    const int baseA = rowA * 80 + kcA * 2;
    const int krB = (lane & 7) + ((lane >> 3) & 1) * 8;
    const int ncB = (lane >> 4) * 8;

    #pragma unroll
    for (int ks = 0; ks < 2; ++ks) {
        uint32_t ahi[4][4], alo[4][4], bhi[4][2], blo[4][2];
        #pragma unroll
        for (int m = 0; m < 4; ++m) {
            const uint32_t off = (wm + m * 16) * 80 + ks * 32 + baseA;
            ldmA(ahi[m], smb + SM_A(buf, 0) + off);
            ldmA(alo[m], smb + SM_A(buf, 1) + off);
        }
        #pragma unroll
        for (int np = 0; np < 2; ++np) {
            const uint32_t off = (ks * 16 + krB) * 272 + (wn + np * 16 + ncB) * 2;
            uint32_t t[4];
            ldmBT(t, smb + SM_B(buf, 0) + off);
            bhi[2*np][0] = t[0]; bhi[2*np][1] = t[1];
            bhi[2*np+1][0] = t[2]; bhi[2*np+1][1] = t[3];
            ldmBT(t, smb + SM_B(buf, 1) + off);
            blo[2*np][0] = t[0]; blo[2*np][1] = t[1];
            blo[2*np+1][0] = t[2]; blo[2*np+1][1] = t[3];
        }
        #pragma unroll
        for (int m = 0; m < 4; ++m)
            #pragma unroll
            for (int n = 0; n < 4; ++n) {
                mma_bf16(acc[m][n], ahi[m], bhi[n]);
                mma_bf16(acc[m][n], ahi[m], blo[n]);
                mma_bf16(acc[m][n], alo[m], bhi[n]);
            }
    }
}

__device__ __forceinline__ void gemm_mainloop(
    uint32_t smb, float acc[4][4][4],
    const __nv_bfloat16* gAhi, const __nv_bfloat16* gAlo,
    const __nv_bfloat16* gBhi, const __nv_bfloat16* gBlo,
    int m0, int n0, int tid, int wm, int wn, int lane)
{
    gemm_load_stage(smb, 0, gAhi, gAlo, gBhi, gBlo, m0, n0, 0, tid);
    int buf = 0;
    for (int s = 0; s < 32; ++s) {
        if (s < 31) {
            gemm_load_stage(smb, buf ^ 1, gAhi, gAlo, gBhi, gBlo,
                            m0, n0, (s + 1) * 32, tid);
            asm volatile("cp.async.wait_group 1;" ::: "memory");
        } else {
            asm volatile("cp.async.wait_group 0;" ::: "memory");
        }
        __syncthreads();
        gemm_compute_stage(smb, buf, acc, wm, wn, lane);
        __syncthreads();
        buf ^= 1;
    }
}

// ---------------------------------------------------------------------------
// Kernel: QKV projection via bf16-split mma.  grid (8, 32, 3), 256 threads.
// ---------------------------------------------------------------------------
__global__ __launch_bounds__(256)
void gemm_qkv_bf16()
{
    extern __shared__ char sm[];
    const uint32_t smb = smem_u32(sm);
    const int tid = threadIdx.x, lane = tid & 31, warp = tid >> 5;
    const int wm = (warp >> 2) * 64, wn = (warp & 3) * 32;
    const int which = blockIdx.z;
    const int m0 = blockIdx.y * 128, n0 = blockIdx.x * 128;
    float* C = (which == 0) ? g_Q : (which == 1) ? g_K : g_V;

    float acc[4][4][4];
    #pragma unroll
    for (int m = 0; m < 4; ++m)
        #pragma unroll
        for (int n = 0; n < 4; ++n)
            #pragma unroll
            for (int e = 0; e < 4; ++e) acc[m][n][e] = 0.f;

    gemm_mainloop(smb, acc, g_Abf[which][0], g_Abf[which][1],
                  g_Wbf[which][0], g_Wbf[which][1], m0, n0, tid, wm, wn, lane);

    // epilogue: write [b,h,l,kc]
    #pragma unroll
    for (int m = 0; m < 4; ++m) {
        const int r0 = m0 + wm + m * 16 + (lane >> 2);
        #pragma unroll
        for (int n = 0; n < 4; ++n) {
            const int col = n0 + wn + n * 8 + (lane & 3) * 2;
            const int h = col >> 6, kc = col & 63;
            {
                const int b = r0 >> 11, l = r0 & 2047;
                float2 v = { acc[m][n][0], acc[m][n][1] };
                *(float2*)&C[(((size_t)(b * NHEADS + h) * SEQ) + l) * DK + kc] = v;
            }
            {
                const int r1 = r0 + 8;
                const int b = r1 >> 11, l = r1 & 2047;
                float2 v = { acc[m][n][2], acc[m][n][3] };
                *(float2*)&C[(((size_t)(b * NHEADS + h) * SEQ) + l) * DK + kc] = v;
            }
        }
    }
}

// ---------------------------------------------------------------------------
// Kernel: output projection via bf16-split mma.  grid (8, 32), 256 threads.
// ---------------------------------------------------------------------------
__global__ __launch_bounds__(256)
void gemm_out_bf16(const float* __restrict__ out_b, float* __restrict__ out)
{
    extern __shared__ char sm[];
    const uint32_t smb = smem_u32(sm);
    const int tid = threadIdx.x, lane = tid & 31, warp = tid >> 5;
    const int wm = (warp >> 2) * 64, wn = (warp & 3) * 32;
    const int m0 = blockIdx.y * 128, n0 = blockIdx.x * 128;

    float acc[4][4][4];
    #pragma unroll
    for (int m = 0; m < 4; ++m)
        #pragma unroll
        for (int n = 0; n < 4; ++n)
            #pragma unroll
            for (int e = 0; e < 4; ++e) acc[m][n][e] = 0.f;

    gemm_mainloop(smb, acc, g_Cbf[0], g_Cbf[1], g_Wobf[0], g_Wobf[1],
                  m0, n0, tid, wm, wn, lane);

    #pragma unroll
    for (int m = 0; m < 4; ++m) {
        const int r0 = m0 + wm + m * 16 + (lane >> 2);
        #pragma unroll
        for (int n = 0; n < 4; ++n) {
            const int col = n0 + wn + n * 8 + (lane & 3) * 2;
            const float b0 = out_b[col], b1 = out_b[col + 1];
            float2 v0 = { acc[m][n][0] + b0, acc[m][n][1] + b1 };
            float2 v1 = { acc[m][n][2] + b0, acc[m][n][3] + b1 };
            *(float2*)&out[(size_t)r0 * DMODEL + col] = v0;
            *(float2*)&out[(size_t)(r0 + 8) * DMODEL + col] = v1;
        }
    }
}

// ---------------------------------------------------------------------------
// Kernel: flash attention (R1 scalar fp32 — known good).
// Phase bias is constant along the softmax axis -> cancels exactly.
// ---------------------------------------------------------------------------
#define SA 65

__global__ __launch_bounds__(256)
void attn_kernel()
{
    extern __shared__ float smf[];
    float* Qs = smf;
    float* Ks = smf + 64 * SA;
    float* Vs = smf + 2 * 64 * SA;
    float* Ps = smf + 3 * 64 * SA;

    const int tid = threadIdx.x;
    const int tx = tid & 15, ty = tid >> 4;
    const int qt = blockIdx.x;
    const int bh = blockIdx.y;

    const float* Qg = g_Q + (size_t)bh * SEQ * DK + (size_t)qt * 64 * DK;
    const float* Kg = g_K + (size_t)bh * SEQ * DK;
    const float* Vg = g_V + (size_t)bh * SEQ * DK;

    for (int i = tid; i < 64 * DK; i += 256)
        Qs[(i >> 6) * SA + (i & 63)] = Qg[i] * 0.125f;

    float acc[4][4] = {};
    float mrow[4], lrow[4];
    #pragma unroll
    for (int i = 0; i < 4; ++i) { mrow[i] = -1e30f; lrow[i] = 0.f; }

    __syncthreads();

    for (int kt = 0; kt < SEQ / 64; ++kt) {
        const float* kp = Kg + (size_t)kt * 64 * DK;
        const float* vp = Vg + (size_t)kt * 64 * DK;
        for (int i = tid; i < 64 * DK; i += 256) {
            int r = i >> 6, c = i & 63;
            Ks[r * SA + c] = kp[i];
            Vs[r * SA + c] = vp[i];
        }
        __syncthreads();

        float s[4][4] = {};
        #pragma unroll 8
        for (int k = 0; k < DK; ++k) {
            float a[4], b[4];
            #pragma unroll
            for (int i = 0; i < 4; ++i) a[i] = Qs[(ty * 4 + i) * SA + k];
            #pragma unroll
            for (int j = 0; j < 4; ++j) b[j] = Ks[(tx * 4 + j) * SA + k];
            #pragma unroll
            for (int i = 0; i < 4; ++i)
                #pragma unroll
                for (int j = 0; j < 4; ++j)
                    s[i][j] = fmaf(a[i], b[j], s[i][j]);
        }

        #pragma unroll
        for (int i = 0; i < 4; ++i) {
            float lm = fmaxf(fmaxf(s[i][0], s[i][1]), fmaxf(s[i][2], s[i][3]));
            #pragma unroll
            for (int off = 8; off > 0; off >>= 1)
                lm = fmaxf(lm, __shfl_xor_sync(0xffffffffu, lm, off));
            const float Mn = fmaxf(mrow[i], lm);
            const float corr = __expf(mrow[i] - Mn);
            float rs = 0.f;
            #pragma unroll
            for (int j = 0; j < 4; ++j) {
                s[i][j] = __expf(s[i][j] - Mn);
                rs += s[i][j];
            }
            #pragma unroll
            for (int off = 8; off > 0; off >>= 1)
                rs += __shfl_xor_sync(0xffffffffu, rs, off);
            lrow[i] = lrow[i] * corr + rs;
            mrow[i] = Mn;
            #pragma unroll
            for (int j = 0; j < 4; ++j) acc[i][j] *= corr;
            #pragma unroll
            for (int j = 0; j < 4; ++j)
                Ps[(ty * 4 + i) * SA + tx * 4 + j] = s[i][j];
        }
        __syncthreads();

        #pragma unroll 8
        for (int k = 0; k < 64; ++k) {
            float a[4], b[4];
            #pragma unroll
            for (int i = 0; i < 4; ++i) a[i] = Ps[(ty * 4 + i) * SA + k];
            #pragma unroll
            for (int j = 0; j < 4; ++j) b[j] = Vs[k * SA + tx * 4 + j];
            #pragma unroll
            for (int i = 0; i < 4; ++i)
                #pragma unroll
                for (int j = 0; j < 4; ++j)
                    acc[i][j] = fmaf(a[i], b[j], acc[i][j]);
        }
        __syncthreads();
    }

    const int b = bh >> 4, h = bh & 15;
    const int l0 = qt * 64;
    #pragma unroll
    for (int i = 0; i < 4; ++i) {
        const float inv = 1.0f / lrow[i];
        float* cp = g_ctx + ((size_t)(b * SEQ + l0 + ty * 4 + i)) * DMODEL
                    + h * DK + tx * 4;
        #pragma unroll
        for (int j = 0; j < 4; ++j) cp[j] = acc[i][j] * inv;
    }
}

// ---------------------------------------------------------------------------
// Launch.  Inputs: query, key, value, Wq, Wk, Wv, out_w, out_b, coupling
// coupling is (correctly) unused: the Kuramoto phase bias is constant along
// the softmax axis and cancels exactly.
// ---------------------------------------------------------------------------
extern "C" void kernel_launch(void* const* d_in, const int* in_sizes, int n_in,
                              void* d_out, int out_size)
{
    const float* q     = (const float*)d_in[0];
    const float* k     = (const float*)d_in[1];
    const float* v     = (const float*)d_in[2];
    const float* wq    = (const float*)d_in[3];
    const float* wk    = (const float*)d_in[4];
    const float* wv    = (const float*)d_in[5];
    const float* out_w = (const float*)d_in[6];
    const float* out_b = (const float*)d_in[7];
    float* out = (float*)d_out;

    // bf16 hi/lo splits
    convert_act_kernel<<<dim3(512, 3), 256>>>(q, k, v);
    convert_w_kernel<<<dim3(256, 3), 256>>>(wq, wk, wv);
    convert_outw_kernel<<<512, 256>>>(out_w);

    // QKV projection (bf16-split mma)
    cudaFuncSetAttribute(gemm_qkv_bf16,
                         cudaFuncAttributeMaxDynamicSharedMemorySize, GSMEM);
    gemm_qkv_bf16<<<dim3(8, 32, 3), 256, GSMEM>>>();

    // attention (fp32 SIMT)
    const int smem = 4 * 64 * SA * sizeof(float);   // 66560
    cudaFuncSetAttribute(attn_kernel,
                         cudaFuncAttributeMaxDynamicSharedMemorySize, smem);
    attn_kernel<<<dim3(SEQ / 64, BATCH * NHEADS), 256, smem>>>();

    // ctx split + output projection (bf16-split mma)
    convert_ctx_kernel<<<1024, 256>>>();
    cudaFuncSetAttribute(gemm_out_bf16,
                         cudaFuncAttributeMaxDynamicSharedMemorySize, GSMEM);
    gemm_out_bf16<<<dim3(8, 32), 256, GSMEM>>>(out_b, out);
}

// round 9
// speedup vs baseline: 2.8799x; 1.8671x over previous
#include <cuda_runtime.h>
#include <cuda_bf16.h>
#include <cstdint>

// Problem constants
#define BATCH 2
#define SEQ   2048
#define DMODEL 1024
#define NHEADS 16
#define DK    64
#define BL    (BATCH*SEQ)          // 4096 rows

// bf16 split operands (ver 0 = hi, ver 1 = lo)
__device__ __align__(16) __nv_bfloat16 g_Abf[3][2][BL*DMODEL];      // q/k/v acts
__device__ __align__(16) __nv_bfloat16 g_Wbf[3][2][DMODEL*DMODEL];  // W packed [d][h*64+kc]
__device__ __align__(16) __nv_bfloat16 g_Wobf[2][DMODEL*DMODEL];    // out_w [d][n]
__device__ __align__(16) __nv_bfloat16 g_Cbf[2][BL*DMODEL];         // ctx hi/lo
// projected Q/K/V in bf16 hi/lo, [b,h,l,dk]; Q pre-scaled by 0.125
__device__ __align__(16) __nv_bfloat16 g_QKVbf[3][2][BATCH*NHEADS*SEQ*DK];

// ---------------------------------------------------------------------------
// PTX helpers (all plain sm_80-class)
// ---------------------------------------------------------------------------
__device__ __forceinline__ uint32_t smem_u32(const void* p) {
    uint32_t a;
    asm("{ .reg .u64 t; cvta.to.shared.u64 t, %1; cvt.u32.u64 %0, t; }"
        : "=r"(a) : "l"(p));
    return a;
}
#define CP16(s, g) \
    asm volatile("cp.async.cg.shared.global [%0], [%1], 16;" :: "r"(s), "l"(g) : "memory")
#define CP_COMMIT() asm volatile("cp.async.commit_group;" ::: "memory")

__device__ __forceinline__ void ldmA(uint32_t r[4], uint32_t addr) {
    asm volatile("ldmatrix.sync.aligned.m8n8.x4.shared.b16 {%0,%1,%2,%3}, [%4];"
                 : "=r"(r[0]), "=r"(r[1]), "=r"(r[2]), "=r"(r[3]) : "r"(addr));
}
__device__ __forceinline__ void ldmBT(uint32_t r[4], uint32_t addr) {
    asm volatile("ldmatrix.sync.aligned.m8n8.x4.trans.shared.b16 {%0,%1,%2,%3}, [%4];"
                 : "=r"(r[0]), "=r"(r[1]), "=r"(r[2]), "=r"(r[3]) : "r"(addr));
}
__device__ __forceinline__ void mma_bf16(float c[4], const uint32_t a[4],
                                         const uint32_t b[2]) {
    asm volatile("mma.sync.aligned.m16n8k16.row.col.f32.bf16.bf16.f32 "
                 "{%0,%1,%2,%3}, {%4,%5,%6,%7}, {%8,%9}, {%0,%1,%2,%3};"
                 : "+f"(c[0]), "+f"(c[1]), "+f"(c[2]), "+f"(c[3])
                 : "r"(a[0]), "r"(a[1]), "r"(a[2]), "r"(a[3]),
                   "r"(b[0]), "r"(b[1]));
}

// ---------------------------------------------------------------------------
// bf16 hi/lo split helpers
// ---------------------------------------------------------------------------
__device__ __forceinline__ void split1(float x, __nv_bfloat16& h, __nv_bfloat16& l) {
    h = __float2bfloat16(x);
    l = __float2bfloat16(x - __bfloat162float(h));
}
// split a pair of floats into packed bf16x2 hi and lo (x0 in low half)
__device__ __forceinline__ void splitpair(float x0, float x1,
                                          uint32_t& hi, uint32_t& lo) {
    __nv_bfloat16 h0, l0, h1, l1;
    split1(x0, h0, l0);
    split1(x1, h1, l1);
    hi = (uint32_t)__bfloat16_as_ushort(h0)
       | ((uint32_t)__bfloat16_as_ushort(h1) << 16);
    lo = (uint32_t)__bfloat16_as_ushort(l0)
       | ((uint32_t)__bfloat16_as_ushort(l1) << 16);
}

// ---------------------------------------------------------------------------
// input conversions
// ---------------------------------------------------------------------------
__global__ void convert_act_kernel(const float* __restrict__ q,
                                   const float* __restrict__ k,
                                   const float* __restrict__ v)
{
    const int which = blockIdx.y;
    const float4* src = (const float4*)(which == 0 ? q : which == 1 ? k : v);
    __nv_bfloat16* hi = g_Abf[which][0];
    __nv_bfloat16* lo = g_Abf[which][1];
    const int n4 = BL * DMODEL / 4;
    for (int i = blockIdx.x * blockDim.x + threadIdx.x; i < n4;
         i += gridDim.x * blockDim.x) {
        float4 x = src[i];
        __nv_bfloat16 h, l;
        split1(x.x, h, l); hi[4*i+0] = h; lo[4*i+0] = l;
        split1(x.y, h, l); hi[4*i+1] = h; lo[4*i+1] = l;
        split1(x.z, h, l); hi[4*i+2] = h; lo[4*i+2] = l;
        split1(x.w, h, l); hi[4*i+3] = h; lo[4*i+3] = l;
    }
}

// W[h][d][kc] -> g_Wbf[which][ver][d*1024 + h*64 + kc]
__global__ void convert_w_kernel(const float* __restrict__ wq,
                                 const float* __restrict__ wk,
                                 const float* __restrict__ wv)
{
    const int which = blockIdx.y;
    const float4* src = (const float4*)(which == 0 ? wq : which == 1 ? wk : wv);
    const int n4 = DMODEL * DMODEL / 4;
    for (int i = blockIdx.x * blockDim.x + threadIdx.x; i < n4;
         i += gridDim.x * blockDim.x) {
        const int flat = i * 4;
        const int h = flat >> 16, d = (flat >> 6) & 1023, kc = flat & 63;
        const int dst = d * DMODEL + h * 64 + kc;
        float4 x = src[i];
        __nv_bfloat16 hh, ll;
        split1(x.x, hh, ll); g_Wbf[which][0][dst+0] = hh; g_Wbf[which][1][dst+0] = ll;
        split1(x.y, hh, ll); g_Wbf[which][0][dst+1] = hh; g_Wbf[which][1][dst+1] = ll;
        split1(x.z, hh, ll); g_Wbf[which][0][dst+2] = hh; g_Wbf[which][1][dst+2] = ll;
        split1(x.w, hh, ll); g_Wbf[which][0][dst+3] = hh; g_Wbf[which][1][dst+3] = ll;
    }
}

__global__ void convert_outw_kernel(const float* __restrict__ src4f)
{
    const float4* src = (const float4*)src4f;
    const int n4 = DMODEL * DMODEL / 4;
    for (int i = blockIdx.x * blockDim.x + threadIdx.x; i < n4;
         i += gridDim.x * blockDim.x) {
        float4 x = src[i];
        __nv_bfloat16 h, l;
        split1(x.x, h, l); g_Wobf[0][4*i+0] = h; g_Wobf[1][4*i+0] = l;
        split1(x.y, h, l); g_Wobf[0][4*i+1] = h; g_Wobf[1][4*i+1] = l;
        split1(x.z, h, l); g_Wobf[0][4*i+2] = h; g_Wobf[1][4*i+2] = l;
        split1(x.w, h, l); g_Wobf[0][4*i+3] = h; g_Wobf[1][4*i+3] = l;
    }
}

// ---------------------------------------------------------------------------
// bf16-split GEMM core (identical to R8's working version)
// ---------------------------------------------------------------------------
#define SM_A(buf, ver) ((buf) * 20480 + (ver) * 10240)
#define SM_B(buf, ver) (40960 + (buf) * 17408 + (ver) * 8704)
#define GSMEM 75776

__device__ __forceinline__ void gemm_load_stage(
    uint32_t smb, int buf,
    const __nv_bfloat16* __restrict__ gAhi, const __nv_bfloat16* __restrict__ gAlo,
    const __nv_bfloat16* __restrict__ gBhi, const __nv_bfloat16* __restrict__ gBlo,
    int m0, int n0, int k0, int tid)
{
    #pragma unroll
    for (int j = 0; j < 4; ++j) {
        const int idx = tid + 256 * j;
        const int ver = idx >> 9, r = idx & 511;
        const int row = r >> 2, c16 = r & 3;
        const __nv_bfloat16* src = (ver ? gAlo : gAhi)
            + (size_t)(m0 + row) * DMODEL + k0 + c16 * 8;
        CP16(smb + SM_A(buf, ver) + row * 80 + c16 * 16, src);
    }
    #pragma unroll
    for (int j = 0; j < 4; ++j) {
        const int idx = tid + 256 * j;
        const int ver = idx >> 9, r = idx & 511;
        const int krow = r >> 4, c16 = r & 15;
        const __nv_bfloat16* src = (ver ? gBlo : gBhi)
            + (size_t)(k0 + krow) * DMODEL + n0 + c16 * 8;
        CP16(smb + SM_B(buf, ver) + krow * 272 + c16 * 16, src);
    }
    CP_COMMIT();
}

__device__ __forceinline__ void gemm_compute_stage(
    uint32_t smb, int buf, float acc[4][4][4], int wm, int wn, int lane)
{
    const int rowA = (lane & 7) + ((lane >> 3) & 1) * 8;
    const int kcA  = (lane >> 4) * 8;
    const int baseA = rowA * 80 + kcA * 2;
    const int krB = (lane & 7) + ((lane >> 3) & 1) * 8;
    const int ncB = (lane >> 4) * 8;

    #pragma unroll
    for (int ks = 0; ks < 2; ++ks) {
        uint32_t ahi[4][4], alo[4][4], bhi[4][2], blo[4][2];
        #pragma unroll
        for (int m = 0; m < 4; ++m) {
            const uint32_t off = (wm + m * 16) * 80 + ks * 32 + baseA;
            ldmA(ahi[m], smb + SM_A(buf, 0) + off);
            ldmA(alo[m], smb + SM_A(buf, 1) + off);
        }
        #pragma unroll
        for (int np = 0; np < 2; ++np) {
            const uint32_t off = (ks * 16 + krB) * 272 + (wn + np * 16 + ncB) * 2;
            uint32_t t[4];
            ldmBT(t, smb + SM_B(buf, 0) + off);
            bhi[2*np][0] = t[0]; bhi[2*np][1] = t[1];
            bhi[2*np+1][0] = t[2]; bhi[2*np+1][1] = t[3];
            ldmBT(t, smb + SM_B(buf, 1) + off);
            blo[2*np][0] = t[0]; blo[2*np][1] = t[1];
            blo[2*np+1][0] = t[2]; blo[2*np+1][1] = t[3];
        }
        #pragma unroll
        for (int m = 0; m < 4; ++m)
            #pragma unroll
            for (int n = 0; n < 4; ++n) {
                mma_bf16(acc[m][n], ahi[m], bhi[n]);
                mma_bf16(acc[m][n], ahi[m], blo[n]);
                mma_bf16(acc[m][n], alo[m], bhi[n]);
            }
    }
}

__device__ __forceinline__ void gemm_mainloop(
    uint32_t smb, float acc[4][4][4],
    const __nv_bfloat16* gAhi, const __nv_bfloat16* gAlo,
    const __nv_bfloat16* gBhi, const __nv_bfloat16* gBlo,
    int m0, int n0, int tid, int wm, int wn, int lane)
{
    gemm_load_stage(smb, 0, gAhi, gAlo, gBhi, gBlo, m0, n0, 0, tid);
    int buf = 0;
    for (int s = 0; s < 32; ++s) {
        if (s < 31) {
            gemm_load_stage(smb, buf ^ 1, gAhi, gAlo, gBhi, gBlo,
                            m0, n0, (s + 1) * 32, tid);
            asm volatile("cp.async.wait_group 1;" ::: "memory");
        } else {
            asm volatile("cp.async.wait_group 0;" ::: "memory");
        }
        __syncthreads();
        gemm_compute_stage(smb, buf, acc, wm, wn, lane);
        __syncthreads();
        buf ^= 1;
    }
}

// ---------------------------------------------------------------------------
// QKV projection: writes bf16 hi/lo Q/K/V directly (Q scaled by 0.125)
// ---------------------------------------------------------------------------
__global__ __launch_bounds__(256)
void gemm_qkv_bf16()
{
    extern __shared__ char sm[];
    const uint32_t smb = smem_u32(sm);
    const int tid = threadIdx.x, lane = tid & 31, warp = tid >> 5;
    const int wm = (warp >> 2) * 64, wn = (warp & 3) * 32;
    const int which = blockIdx.z;
    const int m0 = blockIdx.y * 128, n0 = blockIdx.x * 128;
    __nv_bfloat16* Ch = g_QKVbf[which][0];
    __nv_bfloat16* Cl = g_QKVbf[which][1];
    const float qs = (which == 0) ? 0.125f : 1.0f;

    float acc[4][4][4];
    #pragma unroll
    for (int m = 0; m < 4; ++m)
        #pragma unroll
        for (int n = 0; n < 4; ++n)
            #pragma unroll
            for (int e = 0; e < 4; ++e) acc[m][n][e] = 0.f;

    gemm_mainloop(smb, acc, g_Abf[which][0], g_Abf[which][1],
                  g_Wbf[which][0], g_Wbf[which][1], m0, n0, tid, wm, wn, lane);

    #pragma unroll
    for (int m = 0; m < 4; ++m) {
        const int r0 = m0 + wm + m * 16 + (lane >> 2);
        #pragma unroll
        for (int n = 0; n < 4; ++n) {
            const int col = n0 + wn + n * 8 + (lane & 3) * 2;
            const int h = col >> 6, kc = col & 63;
            uint32_t hi, lo;
            {
                const int b = r0 >> 11, l = r0 & 2047;
                const size_t idx = (((size_t)(b * NHEADS + h) * SEQ) + l) * DK + kc;
                splitpair(acc[m][n][0] * qs, acc[m][n][1] * qs, hi, lo);
                *(uint32_t*)&Ch[idx] = hi;
                *(uint32_t*)&Cl[idx] = lo;
            }
            {
                const int r1 = r0 + 8;
                const int b = r1 >> 11, l = r1 & 2047;
                const size_t idx = (((size_t)(b * NHEADS + h) * SEQ) + l) * DK + kc;
                splitpair(acc[m][n][2] * qs, acc[m][n][3] * qs, hi, lo);
                *(uint32_t*)&Ch[idx] = hi;
                *(uint32_t*)&Cl[idx] = lo;
            }
        }
    }
}

// ---------------------------------------------------------------------------
// Output projection (unchanged)
// ---------------------------------------------------------------------------
__global__ __launch_bounds__(256)
void gemm_out_bf16(const float* __restrict__ out_b, float* __restrict__ out)
{
    extern __shared__ char sm[];
    const uint32_t smb = smem_u32(sm);
    const int tid = threadIdx.x, lane = tid & 31, warp = tid >> 5;
    const int wm = (warp >> 2) * 64, wn = (warp & 3) * 32;
    const int m0 = blockIdx.y * 128, n0 = blockIdx.x * 128;

    float acc[4][4][4];
    #pragma unroll
    for (int m = 0; m < 4; ++m)
        #pragma unroll
        for (int n = 0; n < 4; ++n)
            #pragma unroll
            for (int e = 0; e < 4; ++e) acc[m][n][e] = 0.f;

    gemm_mainloop(smb, acc, g_Cbf[0], g_Cbf[1], g_Wobf[0], g_Wobf[1],
                  m0, n0, tid, wm, wn, lane);

    #pragma unroll
    for (int m = 0; m < 4; ++m) {
        const int r0 = m0 + wm + m * 16 + (lane >> 2);
        #pragma unroll
        for (int n = 0; n < 4; ++n) {
            const int col = n0 + wn + n * 8 + (lane & 3) * 2;
            const float b0 = out_b[col], b1 = out_b[col + 1];
            float2 v0 = { acc[m][n][0] + b0, acc[m][n][1] + b1 };
            float2 v1 = { acc[m][n][2] + b0, acc[m][n][3] + b1 };
            *(float2*)&out[(size_t)r0 * DMODEL + col] = v0;
            *(float2*)&out[(size_t)(r0 + 8) * DMODEL + col] = v1;
        }
    }
}

// ---------------------------------------------------------------------------
// Tensor-core flash attention.  CTA = 64 q-rows x (b,h); 4 warps x 16 rows.
// S = QK^T: A = Q [m][k] (ldmatrix non-trans), B = K [n][k] (non-trans).
// O = PV:   A = P (register frags from S), B = V [k][n] (trans ldmatrix).
// Both products use the 3-term hi/lo split.  Phase bias cancels in softmax.
// smem: Q hi/lo + double-buffered K/V hi/lo; 144B row stride (conflict-free).
// ---------------------------------------------------------------------------
#define ATT_SMEM 92160   // 2*9216 (Q) + 2*4*9216 (KV double buffer)

__device__ __forceinline__ void kv_load(
    uint32_t smb, int buf,
    const __nv_bfloat16* kh, const __nv_bfloat16* kl,
    const __nv_bfloat16* vh, const __nv_bfloat16* vl,
    int kt, int tid)
{
    const uint32_t base = smb + 18432 + buf * 36864;
    const size_t goff = (size_t)kt * 64 * DK;
    #pragma unroll
    for (int j = 0; j < 16; ++j) {
        const int idx = tid + 128 * j;
        const int sel = idx >> 9, r = idx & 511;
        const int row = r >> 3, c16 = r & 7;
        const __nv_bfloat16* src =
            (sel == 0 ? kh : sel == 1 ? kl : sel == 2 ? vh : vl)
            + goff + row * DK + c16 * 8;
        CP16(base + sel * 9216 + row * 144 + c16 * 16, src);
    }
    CP_COMMIT();
}

__global__ __launch_bounds__(128)
void attn_mma_kernel()
{
    extern __shared__ char sm[];
    const uint32_t smb = smem_u32(sm);
    const int tid = threadIdx.x, lane = tid & 31, wid = tid >> 5;
    const int qt = blockIdx.x, bh = blockIdx.y;
    const size_t bhoff = (size_t)bh * SEQ * DK;

    const __nv_bfloat16* gQh = g_QKVbf[0][0] + bhoff + (size_t)qt * 64 * DK;
    const __nv_bfloat16* gQl = g_QKVbf[0][1] + bhoff + (size_t)qt * 64 * DK;
    const __nv_bfloat16* gKh = g_QKVbf[1][0] + bhoff;
    const __nv_bfloat16* gKl = g_QKVbf[1][1] + bhoff;
    const __nv_bfloat16* gVh = g_QKVbf[2][0] + bhoff;
    const __nv_bfloat16* gVl = g_QKVbf[2][1] + bhoff;

    // Q tile load (group 0)
    #pragma unroll
    for (int j = 0; j < 8; ++j) {
        const int idx = tid + 128 * j;
        const int ver = idx >> 9, r = idx & 511;
        const int row = r >> 3, c16 = r & 7;
        CP16(smb + ver * 9216 + row * 144 + c16 * 16,
             (ver ? gQl : gQh) + row * DK + c16 * 8);
    }
    CP_COMMIT();
    kv_load(smb, 0, gKh, gKl, gVh, gVl, 0, tid);   // group 1

    asm volatile("cp.async.wait_group 1;" ::: "memory");  // Q ready
    __syncthreads();

    // Q fragments (held for the whole kernel)
    uint32_t aQh[4][4], aQl[4][4];
    {
        const int rowA = (lane & 7) + ((lane >> 3) & 1) * 8;
        const int kcA  = (lane >> 4) * 8;
        #pragma unroll
        for (int ks = 0; ks < 4; ++ks) {
            const uint32_t off = (wid * 16 + rowA) * 144 + (ks * 16 + kcA) * 2;
            ldmA(aQh[ks], smb + off);
            ldmA(aQl[ks], smb + 9216 + off);
        }
    }

    float oc[8][4];
    #pragma unroll
    for (int f = 0; f < 8; ++f)
        #pragma unroll
        for (int e = 0; e < 4; ++e) oc[f][e] = 0.f;
    float mrow0 = -1e30f, mrow1 = -1e30f, lrow0 = 0.f, lrow1 = 0.f;

    const uint32_t krow  = (lane & 7) + ((lane >> 4) & 1) * 8;  // K b-frag rows
    const uint32_t kboff = ((lane >> 3) & 1) * 16;
    const int krB = (lane & 7) + ((lane >> 3) & 1) * 8;         // V b-frag rows
    const int ncB = (lane >> 4) * 8;

    for (int kt = 0; kt < 32; ++kt) {
        const int buf = kt & 1;
        if (kt < 31) {
            kv_load(smb, buf ^ 1, gKh, gKl, gVh, gVl, kt + 1, tid);
            asm volatile("cp.async.wait_group 1;" ::: "memory");
        } else {
            asm volatile("cp.async.wait_group 0;" ::: "memory");
        }
        __syncthreads();
        const uint32_t KH = smb + 18432 + buf * 36864;
        const uint32_t KL = KH + 9216;
        const uint32_t VH = KH + 18432;
        const uint32_t VL = KH + 27648;

        // ---- S = Q K^T (3-term split) ----
        float sc[8][4];
        #pragma unroll
        for (int f = 0; f < 8; ++f)
            #pragma unroll
            for (int e = 0; e < 4; ++e) sc[f][e] = 0.f;

        #pragma unroll
        for (int ks = 0; ks < 4; ++ks) {
            #pragma unroll
            for (int g = 0; g < 4; ++g) {
                uint32_t th[4], tl[4];
                const uint32_t off = (g * 16 + krow) * 144 + ks * 32 + kboff;
                ldmA(th, KH + off);
                ldmA(tl, KL + off);
                uint32_t b0h[2] = { th[0], th[1] }, b1h[2] = { th[2], th[3] };
                uint32_t b0l[2] = { tl[0], tl[1] }, b1l[2] = { tl[2], tl[3] };
                mma_bf16(sc[2*g],   aQh[ks], b0h);
                mma_bf16(sc[2*g],   aQh[ks], b0l);
                mma_bf16(sc[2*g],   aQl[ks], b0h);
                mma_bf16(sc[2*g+1], aQh[ks], b1h);
                mma_bf16(sc[2*g+1], aQh[ks], b1l);
                mma_bf16(sc[2*g+1], aQl[ks], b1h);
            }
        }

        // ---- online softmax (rows live inside a quad) ----
        float mn0 = -1e30f, mn1 = -1e30f;
        #pragma unroll
        for (int f = 0; f < 8; ++f) {
            mn0 = fmaxf(mn0, fmaxf(sc[f][0], sc[f][1]));
            mn1 = fmaxf(mn1, fmaxf(sc[f][2], sc[f][3]));
        }
        mn0 = fmaxf(mn0, __shfl_xor_sync(0xffffffffu, mn0, 1));
        mn0 = fmaxf(mn0, __shfl_xor_sync(0xffffffffu, mn0, 2));
        mn1 = fmaxf(mn1, __shfl_xor_sync(0xffffffffu, mn1, 1));
        mn1 = fmaxf(mn1, __shfl_xor_sync(0xffffffffu, mn1, 2));
        const float M0 = fmaxf(mrow0, mn0), M1 = fmaxf(mrow1, mn1);
        const float c0 = __expf(mrow0 - M0), c1 = __expf(mrow1 - M1);
        float rs0 = 0.f, rs1 = 0.f;
        #pragma unroll
        for (int f = 0; f < 8; ++f) {
            sc[f][0] = __expf(sc[f][0] - M0); rs0 += sc[f][0];
            sc[f][1] = __expf(sc[f][1] - M0); rs0 += sc[f][1];
            sc[f][2] = __expf(sc[f][2] - M1); rs1 += sc[f][2];
            sc[f][3] = __expf(sc[f][3] - M1); rs1 += sc[f][3];
        }
        rs0 += __shfl_xor_sync(0xffffffffu, rs0, 1);
        rs0 += __shfl_xor_sync(0xffffffffu, rs0, 2);
        rs1 += __shfl_xor_sync(0xffffffffu, rs1, 1);
        rs1 += __shfl_xor_sync(0xffffffffu, rs1, 2);
        lrow0 = lrow0 * c0 + rs0;
        lrow1 = lrow1 * c1 + rs1;
        mrow0 = M0; mrow1 = M1;
        #pragma unroll
        for (int f = 0; f < 8; ++f) {
            oc[f][0] *= c0; oc[f][1] *= c0;
            oc[f][2] *= c1; oc[f][3] *= c1;
        }

        // ---- pack P fragments (C-frag -> A-frag layout, in registers) ----
        uint32_t aPh[4][4], aPl[4][4];
        #pragma unroll
        for (int ks = 0; ks < 4; ++ks) {
            const int f0 = 2 * ks, f1 = 2 * ks + 1;
            splitpair(sc[f0][0], sc[f0][1], aPh[ks][0], aPl[ks][0]);
            splitpair(sc[f0][2], sc[f0][3], aPh[ks][1], aPl[ks][1]);
            splitpair(sc[f1][0], sc[f1][1], aPh[ks][2], aPl[ks][2]);
            splitpair(sc[f1][2], sc[f1][3], aPh[ks][3], aPl[ks][3]);
        }

        // ---- O += P V (3-term split) ----
        #pragma unroll
        for (int ks = 0; ks < 4; ++ks) {
            #pragma unroll
            for (int g = 0; g < 4; ++g) {
                uint32_t th[4], tl[4];
                const uint32_t off = (ks * 16 + krB) * 144 + (g * 16 + ncB) * 2;
                ldmBT(th, VH + off);
                ldmBT(tl, VL + off);
                uint32_t b0h[2] = { th[0], th[1] }, b1h[2] = { th[2], th[3] };
                uint32_t b0l[2] = { tl[0], tl[1] }, b1l[2] = { tl[2], tl[3] };
                mma_bf16(oc[2*g],   aPh[ks], b0h);
                mma_bf16(oc[2*g],   aPh[ks], b0l);
                mma_bf16(oc[2*g],   aPl[ks], b0h);
                mma_bf16(oc[2*g+1], aPh[ks], b1h);
                mma_bf16(oc[2*g+1], aPh[ks], b1l);
                mma_bf16(oc[2*g+1], aPl[ks], b1h);
            }
        }
        __syncthreads();
    }

    // ---- epilogue: normalize, split, write ctx bf16 hi/lo ----
    const int b = bh >> 4, h = bh & 15;
    const float i0 = 1.0f / lrow0, i1 = 1.0f / lrow1;
    const int lg0 = qt * 64 + wid * 16 + (lane >> 2);
    const int lg1 = lg0 + 8;
    #pragma unroll
    for (int f = 0; f < 8; ++f) {
        const int col = h * 64 + 8 * f + (lane & 3) * 2;
        uint32_t hi, lo;
        splitpair(oc[f][0] * i0, oc[f][1] * i0, hi, lo);
        const size_t idx0 = ((size_t)(b * SEQ + lg0)) * DMODEL + col;
        *(uint32_t*)&g_Cbf[0][idx0] = hi;
        *(uint32_t*)&g_Cbf[1][idx0] = lo;
        splitpair(oc[f][2] * i1, oc[f][3] * i1, hi, lo);
        const size_t idx1 = ((size_t)(b * SEQ + lg1)) * DMODEL + col;
        *(uint32_t*)&g_Cbf[0][idx1] = hi;
        *(uint32_t*)&g_Cbf[1][idx1] = lo;
    }
}

// ---------------------------------------------------------------------------
// Launch.  Inputs: query, key, value, Wq, Wk, Wv, out_w, out_b, coupling
// coupling is (correctly) unused: the Kuramoto phase bias is constant along
// the softmax axis and cancels exactly.
// ---------------------------------------------------------------------------
extern "C" void kernel_launch(void* const* d_in, const int* in_sizes, int n_in,
                              void* d_out, int out_size)
{
    const float* q     = (const float*)d_in[0];
    const float* k     = (const float*)d_in[1];
    const float* v     = (const float*)d_in[2];
    const float* wq    = (const float*)d_in[3];
    const float* wk    = (const float*)d_in[4];
    const float* wv    = (const float*)d_in[5];
    const float* out_w = (const float*)d_in[6];
    const float* out_b = (const float*)d_in[7];
    float* out = (float*)d_out;

    // bf16 hi/lo splits of inputs
    convert_act_kernel<<<dim3(512, 3), 256>>>(q, k, v);
    convert_w_kernel<<<dim3(256, 3), 256>>>(wq, wk, wv);
    convert_outw_kernel<<<512, 256>>>(out_w);

    // QKV projection -> bf16 Q/K/V (Q pre-scaled)
    cudaFuncSetAttribute(gemm_qkv_bf16,
                         cudaFuncAttributeMaxDynamicSharedMemorySize, GSMEM);
    gemm_qkv_bf16<<<dim3(8, 32, 3), 256, GSMEM>>>();

    // tensor-core flash attention -> ctx bf16 hi/lo
    cudaFuncSetAttribute(attn_mma_kernel,
                         cudaFuncAttributeMaxDynamicSharedMemorySize, ATT_SMEM);
    attn_mma_kernel<<<dim3(SEQ / 64, BATCH * NHEADS), 128, ATT_SMEM>>>();

    // output projection
    cudaFuncSetAttribute(gemm_out_bf16,
                         cudaFuncAttributeMaxDynamicSharedMemorySize, GSMEM);
    gemm_out_bf16<<<dim3(8, 32), 256, GSMEM>>>(out_b, out);
}

// round 10
// speedup vs baseline: 3.0452x; 1.0574x over previous
#include <cuda_runtime.h>
#include <cuda_bf16.h>
#include <cstdint>

// Problem constants
#define BATCH 2
#define SEQ   2048
#define DMODEL 1024
#define NHEADS 16
#define DK    64
#define BL    (BATCH*SEQ)          // 4096 rows

// bf16 split operands (ver 0 = hi, ver 1 = lo)
__device__ __align__(16) __nv_bfloat16 g_Abf[3][2][BL*DMODEL];      // q/k/v acts
__device__ __align__(16) __nv_bfloat16 g_Wbf[3][2][DMODEL*DMODEL];  // W packed [d][h*64+kc]
__device__ __align__(16) __nv_bfloat16 g_Wobf[2][DMODEL*DMODEL];    // out_w [d][n]
__device__ __align__(16) __nv_bfloat16 g_Cbf[2][BL*DMODEL];         // ctx hi/lo
// projected Q/K/V in bf16 hi/lo, [b,h,l,dk]; Q pre-scaled by 0.125
__device__ __align__(16) __nv_bfloat16 g_QKVbf[3][2][BATCH*NHEADS*SEQ*DK];

// ---------------------------------------------------------------------------
// PTX helpers (all plain sm_80-class)
// ---------------------------------------------------------------------------
__device__ __forceinline__ uint32_t smem_u32(const void* p) {
    uint32_t a;
    asm("{ .reg .u64 t; cvta.to.shared.u64 t, %1; cvt.u32.u64 %0, t; }"
        : "=r"(a) : "l"(p));
    return a;
}
#define CP16(s, g) \
    asm volatile("cp.async.cg.shared.global [%0], [%1], 16;" :: "r"(s), "l"(g) : "memory")
#define CP_COMMIT() asm volatile("cp.async.commit_group;" ::: "memory")

__device__ __forceinline__ void ldmA(uint32_t r[4], uint32_t addr) {
    asm volatile("ldmatrix.sync.aligned.m8n8.x4.shared.b16 {%0,%1,%2,%3}, [%4];"
                 : "=r"(r[0]), "=r"(r[1]), "=r"(r[2]), "=r"(r[3]) : "r"(addr));
}
__device__ __forceinline__ void ldmBT(uint32_t r[4], uint32_t addr) {
    asm volatile("ldmatrix.sync.aligned.m8n8.x4.trans.shared.b16 {%0,%1,%2,%3}, [%4];"
                 : "=r"(r[0]), "=r"(r[1]), "=r"(r[2]), "=r"(r[3]) : "r"(addr));
}
__device__ __forceinline__ void mma_bf16(float c[4], const uint32_t a[4],
                                         const uint32_t b[2]) {
    asm volatile("mma.sync.aligned.m16n8k16.row.col.f32.bf16.bf16.f32 "
                 "{%0,%1,%2,%3}, {%4,%5,%6,%7}, {%8,%9}, {%0,%1,%2,%3};"
                 : "+f"(c[0]), "+f"(c[1]), "+f"(c[2]), "+f"(c[3])
                 : "r"(a[0]), "r"(a[1]), "r"(a[2]), "r"(a[3]),
                   "r"(b[0]), "r"(b[1]));
}

// ---------------------------------------------------------------------------
// bf16 hi/lo split helpers
// ---------------------------------------------------------------------------
__device__ __forceinline__ void split1(float x, __nv_bfloat16& h, __nv_bfloat16& l) {
    h = __float2bfloat16(x);
    l = __float2bfloat16(x - __bfloat162float(h));
}
__device__ __forceinline__ void splitpair(float x0, float x1,
                                          uint32_t& hi, uint32_t& lo) {
    __nv_bfloat16 h0, l0, h1, l1;
    split1(x0, h0, l0);
    split1(x1, h1, l1);
    hi = (uint32_t)__bfloat16_as_ushort(h0)
       | ((uint32_t)__bfloat16_as_ushort(h1) << 16);
    lo = (uint32_t)__bfloat16_as_ushort(l0)
       | ((uint32_t)__bfloat16_as_ushort(l1) << 16);
}

// ---------------------------------------------------------------------------
// input conversions
// ---------------------------------------------------------------------------
__global__ void convert_act_kernel(const float* __restrict__ q,
                                   const float* __restrict__ k,
                                   const float* __restrict__ v)
{
    const int which = blockIdx.y;
    const float4* src = (const float4*)(which == 0 ? q : which == 1 ? k : v);
    __nv_bfloat16* hi = g_Abf[which][0];
    __nv_bfloat16* lo = g_Abf[which][1];
    const int n4 = BL * DMODEL / 4;
    for (int i = blockIdx.x * blockDim.x + threadIdx.x; i < n4;
         i += gridDim.x * blockDim.x) {
        float4 x = src[i];
        __nv_bfloat16 h, l;
        split1(x.x, h, l); hi[4*i+0] = h; lo[4*i+0] = l;
        split1(x.y, h, l); hi[4*i+1] = h; lo[4*i+1] = l;
        split1(x.z, h, l); hi[4*i+2] = h; lo[4*i+2] = l;
        split1(x.w, h, l); hi[4*i+3] = h; lo[4*i+3] = l;
    }
}

// W[h][d][kc] -> g_Wbf[which][ver][d*1024 + h*64 + kc]
__global__ void convert_w_kernel(const float* __restrict__ wq,
                                 const float* __restrict__ wk,
                                 const float* __restrict__ wv)
{
    const int which = blockIdx.y;
    const float4* src = (const float4*)(which == 0 ? wq : which == 1 ? wk : wv);
    const int n4 = DMODEL * DMODEL / 4;
    for (int i = blockIdx.x * blockDim.x + threadIdx.x; i < n4;
         i += gridDim.x * blockDim.x) {
        const int flat = i * 4;
        const int h = flat >> 16, d = (flat >> 6) & 1023, kc = flat & 63;
        const int dst = d * DMODEL + h * 64 + kc;
        float4 x = src[i];
        __nv_bfloat16 hh, ll;
        split1(x.x, hh, ll); g_Wbf[which][0][dst+0] = hh; g_Wbf[which][1][dst+0] = ll;
        split1(x.y, hh, ll); g_Wbf[which][0][dst+1] = hh; g_Wbf[which][1][dst+1] = ll;
        split1(x.z, hh, ll); g_Wbf[which][0][dst+2] = hh; g_Wbf[which][1][dst+2] = ll;
        split1(x.w, hh, ll); g_Wbf[which][0][dst+3] = hh; g_Wbf[which][1][dst+3] = ll;
    }
}

__global__ void convert_outw_kernel(const float* __restrict__ src4f)
{
    const float4* src = (const float4*)src4f;
    const int n4 = DMODEL * DMODEL / 4;
    for (int i = blockIdx.x * blockDim.x + threadIdx.x; i < n4;
         i += gridDim.x * blockDim.x) {
        float4 x = src[i];
        __nv_bfloat16 h, l;
        split1(x.x, h, l); g_Wobf[0][4*i+0] = h; g_Wobf[1][4*i+0] = l;
        split1(x.y, h, l); g_Wobf[0][4*i+1] = h; g_Wobf[1][4*i+1] = l;
        split1(x.z, h, l); g_Wobf[0][4*i+2] = h; g_Wobf[1][4*i+2] = l;
        split1(x.w, h, l); g_Wobf[0][4*i+3] = h; g_Wobf[1][4*i+3] = l;
    }
}

// ---------------------------------------------------------------------------
// bf16-split GEMM core: 3-stage cp.async pipeline, ONE sync per stage.
// stage layout: A hi/lo (2 x 10240, stride 80B) + B hi/lo (2 x 8704, 272B).
// ---------------------------------------------------------------------------
#define STG_BYTES 37888
#define SM_A(st, ver) ((st) * STG_BYTES + (ver) * 10240)
#define SM_B(st, ver) ((st) * STG_BYTES + 20480 + (ver) * 8704)
#define GSMEM (3 * STG_BYTES)   // 113664

__device__ __forceinline__ void gemm_load_stage(
    uint32_t smb, int st,
    const __nv_bfloat16* __restrict__ gAhi, const __nv_bfloat16* __restrict__ gAlo,
    const __nv_bfloat16* __restrict__ gBhi, const __nv_bfloat16* __restrict__ gBlo,
    int m0, int n0, int k0, int tid)
{
    #pragma unroll
    for (int j = 0; j < 4; ++j) {
        const int idx = tid + 256 * j;
        const int ver = idx >> 9, r = idx & 511;
        const int row = r >> 2, c16 = r & 3;
        const __nv_bfloat16* src = (ver ? gAlo : gAhi)
            + (size_t)(m0 + row) * DMODEL + k0 + c16 * 8;
        CP16(smb + SM_A(st, ver) + row * 80 + c16 * 16, src);
    }
    #pragma unroll
    for (int j = 0; j < 4; ++j) {
        const int idx = tid + 256 * j;
        const int ver = idx >> 9, r = idx & 511;
        const int krow = r >> 4, c16 = r & 15;
        const __nv_bfloat16* src = (ver ? gBlo : gBhi)
            + (size_t)(k0 + krow) * DMODEL + n0 + c16 * 8;
        CP16(smb + SM_B(st, ver) + krow * 272 + c16 * 16, src);
    }
    CP_COMMIT();
}

__device__ __forceinline__ void gemm_compute_stage(
    uint32_t smb, int st, float acc[4][4][4], int wm, int wn, int lane)
{
    const int rowA = (lane & 7) + ((lane >> 3) & 1) * 8;
    const int kcA  = (lane >> 4) * 8;
    const int baseA = rowA * 80 + kcA * 2;
    const int krB = (lane & 7) + ((lane >> 3) & 1) * 8;
    const int ncB = (lane >> 4) * 8;

    #pragma unroll
    for (int ks = 0; ks < 2; ++ks) {
        uint32_t ahi[4][4], alo[4][4], bhi[4][2], blo[4][2];
        #pragma unroll
        for (int m = 0; m < 4; ++m) {
            const uint32_t off = (wm + m * 16) * 80 + ks * 32 + baseA;
            ldmA(ahi[m], smb + SM_A(st, 0) + off);
            ldmA(alo[m], smb + SM_A(st, 1) + off);
        }
        #pragma unroll
        for (int np = 0; np < 2; ++np) {
            const uint32_t off = (ks * 16 + krB) * 272 + (wn + np * 16 + ncB) * 2;
            uint32_t t[4];
            ldmBT(t, smb + SM_B(st, 0) + off);
            bhi[2*np][0] = t[0]; bhi[2*np][1] = t[1];
            bhi[2*np+1][0] = t[2]; bhi[2*np+1][1] = t[3];
            ldmBT(t, smb + SM_B(st, 1) + off);
            blo[2*np][0] = t[0]; blo[2*np][1] = t[1];
            blo[2*np+1][0] = t[2]; blo[2*np+1][1] = t[3];
        }
        #pragma unroll
        for (int m = 0; m < 4; ++m)
            #pragma unroll
            for (int n = 0; n < 4; ++n) {
                mma_bf16(acc[m][n], ahi[m], bhi[n]);
                mma_bf16(acc[m][n], ahi[m], blo[n]);
                mma_bf16(acc[m][n], alo[m], bhi[n]);
            }
    }
}

__device__ __forceinline__ void gemm_mainloop(
    uint32_t smb, float acc[4][4][4],
    const __nv_bfloat16* gAhi, const __nv_bfloat16* gAlo,
    const __nv_bfloat16* gBhi, const __nv_bfloat16* gBlo,
    int m0, int n0, int tid, int wm, int wn, int lane)
{
    gemm_load_stage(smb, 0, gAhi, gAlo, gBhi, gBlo, m0, n0, 0, tid);
    gemm_load_stage(smb, 1, gAhi, gAlo, gBhi, gBlo, m0, n0, 32, tid);
    for (int s = 0; s < 32; ++s) {
        if (s < 31)
            asm volatile("cp.async.wait_group 1;" ::: "memory");
        else
            asm volatile("cp.async.wait_group 0;" ::: "memory");
        __syncthreads();
        if (s + 2 < 32)
            gemm_load_stage(smb, (s + 2) % 3, gAhi, gAlo, gBhi, gBlo,
                            m0, n0, (s + 2) * 32, tid);
        gemm_compute_stage(smb, s % 3, acc, wm, wn, lane);
    }
}

// ---------------------------------------------------------------------------
// QKV projection: writes bf16 hi/lo Q/K/V directly (Q scaled by 0.125)
// ---------------------------------------------------------------------------
__global__ __launch_bounds__(256, 2)
void gemm_qkv_bf16()
{
    extern __shared__ char sm[];
    const uint32_t smb = smem_u32(sm);
    const int tid = threadIdx.x, lane = tid & 31, warp = tid >> 5;
    const int wm = (warp >> 2) * 64, wn = (warp & 3) * 32;
    const int which = blockIdx.z;
    const int m0 = blockIdx.y * 128, n0 = blockIdx.x * 128;
    __nv_bfloat16* Ch = g_QKVbf[which][0];
    __nv_bfloat16* Cl = g_QKVbf[which][1];
    const float qs = (which == 0) ? 0.125f : 1.0f;

    float acc[4][4][4];
    #pragma unroll
    for (int m = 0; m < 4; ++m)
        #pragma unroll
        for (int n = 0; n < 4; ++n)
            #pragma unroll
            for (int e = 0; e < 4; ++e) acc[m][n][e] = 0.f;

    gemm_mainloop(smb, acc, g_Abf[which][0], g_Abf[which][1],
                  g_Wbf[which][0], g_Wbf[which][1], m0, n0, tid, wm, wn, lane);

    #pragma unroll
    for (int m = 0; m < 4; ++m) {
        const int r0 = m0 + wm + m * 16 + (lane >> 2);
        #pragma unroll
        for (int n = 0; n < 4; ++n) {
            const int col = n0 + wn + n * 8 + (lane & 3) * 2;
            const int h = col >> 6, kc = col & 63;
            uint32_t hi, lo;
            {
                const int b = r0 >> 11, l = r0 & 2047;
                const size_t idx = (((size_t)(b * NHEADS + h) * SEQ) + l) * DK + kc;
                splitpair(acc[m][n][0] * qs, acc[m][n][1] * qs, hi, lo);
                *(uint32_t*)&Ch[idx] = hi;
                *(uint32_t*)&Cl[idx] = lo;
            }
            {
                const int r1 = r0 + 8;
                const int b = r1 >> 11, l = r1 & 2047;
                const size_t idx = (((size_t)(b * NHEADS + h) * SEQ) + l) * DK + kc;
                splitpair(acc[m][n][2] * qs, acc[m][n][3] * qs, hi, lo);
                *(uint32_t*)&Ch[idx] = hi;
                *(uint32_t*)&Cl[idx] = lo;
            }
        }
    }
}

// ---------------------------------------------------------------------------
// Output projection
// ---------------------------------------------------------------------------
__global__ __launch_bounds__(256, 2)
void gemm_out_bf16(const float* __restrict__ out_b, float* __restrict__ out)
{
    extern __shared__ char sm[];
    const uint32_t smb = smem_u32(sm);
    const int tid = threadIdx.x, lane = tid & 31, warp = tid >> 5;
    const int wm = (warp >> 2) * 64, wn = (warp & 3) * 32;
    const int m0 = blockIdx.y * 128, n0 = blockIdx.x * 128;

    float acc[4][4][4];
    #pragma unroll
    for (int m = 0; m < 4; ++m)
        #pragma unroll
        for (int n = 0; n < 4; ++n)
            #pragma unroll
            for (int e = 0; e < 4; ++e) acc[m][n][e] = 0.f;

    gemm_mainloop(smb, acc, g_Cbf[0], g_Cbf[1], g_Wobf[0], g_Wobf[1],
                  m0, n0, tid, wm, wn, lane);

    #pragma unroll
    for (int m = 0; m < 4; ++m) {
        const int r0 = m0 + wm + m * 16 + (lane >> 2);
        #pragma unroll
        for (int n = 0; n < 4; ++n) {
            const int col = n0 + wn + n * 8 + (lane & 3) * 2;
            const float b0 = out_b[col], b1 = out_b[col + 1];
            float2 v0 = { acc[m][n][0] + b0, acc[m][n][1] + b1 };
            float2 v1 = { acc[m][n][2] + b0, acc[m][n][3] + b1 };
            *(float2*)&out[(size_t)r0 * DMODEL + col] = v0;
            *(float2*)&out[(size_t)(r0 + 8) * DMODEL + col] = v1;
        }
    }
}

// ---------------------------------------------------------------------------
// Tensor-core flash attention.  CTA = 128 q-rows x (b,h); 8 warps x 16 rows.
// Per-warp fragment code identical to R9 (validated); KV ring is now 3-stage
// with ONE sync per tile.  Phase bias cancels in softmax.
// smem: Q hi/lo (36864) + 3 x KV stage (36864 each) = 147456.
// ---------------------------------------------------------------------------
#define ATT_SMEM (36864 + 3 * 36864)   // 147456

__device__ __forceinline__ void kv_load(
    uint32_t smb, int buf,
    const __nv_bfloat16* kh, const __nv_bfloat16* kl,
    const __nv_bfloat16* vh, const __nv_bfloat16* vl,
    int kt, int tid)
{
    const uint32_t base = smb + 36864 + buf * 36864;
    const size_t goff = (size_t)kt * 64 * DK;
    #pragma unroll
    for (int j = 0; j < 8; ++j) {
        const int idx = tid + 256 * j;
        const int sel = idx >> 9, r = idx & 511;
        const int row = r >> 3, c16 = r & 7;
        const __nv_bfloat16* src =
            (sel == 0 ? kh : sel == 1 ? kl : sel == 2 ? vh : vl)
            + goff + row * DK + c16 * 8;
        CP16(base + sel * 9216 + row * 144 + c16 * 16, src);
    }
    CP_COMMIT();
}

__global__ __launch_bounds__(256)
void attn_mma_kernel()
{
    extern __shared__ char sm[];
    const uint32_t smb = smem_u32(sm);
    const int tid = threadIdx.x, lane = tid & 31, wid = tid >> 5;  // 0..7
    const int qt = blockIdx.x, bh = blockIdx.y;
    const size_t bhoff = (size_t)bh * SEQ * DK;

    const __nv_bfloat16* gQh = g_QKVbf[0][0] + bhoff + (size_t)qt * 128 * DK;
    const __nv_bfloat16* gQl = g_QKVbf[0][1] + bhoff + (size_t)qt * 128 * DK;
    const __nv_bfloat16* gKh = g_QKVbf[1][0] + bhoff;
    const __nv_bfloat16* gKl = g_QKVbf[1][1] + bhoff;
    const __nv_bfloat16* gVh = g_QKVbf[2][0] + bhoff;
    const __nv_bfloat16* gVl = g_QKVbf[2][1] + bhoff;

    // Q tile load (group 0): 2 ver x 128 rows x 8 chunks = 2048
    #pragma unroll
    for (int j = 0; j < 8; ++j) {
        const int idx = tid + 256 * j;
        const int ver = idx >> 10, r = idx & 1023;
        const int row = r >> 3, c16 = r & 7;
        CP16(smb + ver * 18432 + row * 144 + c16 * 16,
             (ver ? gQl : gQh) + row * DK + c16 * 8);
    }
    CP_COMMIT();
    kv_load(smb, 0, gKh, gKl, gVh, gVl, 0, tid);   // group 1
    kv_load(smb, 1, gKh, gKl, gVh, gVl, 1, tid);   // group 2

    asm volatile("cp.async.wait_group 2;" ::: "memory");  // Q ready
    __syncthreads();

    // Q fragments (held for the whole kernel)
    uint32_t aQh[4][4], aQl[4][4];
    {
        const int rowA = (lane & 7) + ((lane >> 3) & 1) * 8;
        const int kcA  = (lane >> 4) * 8;
        #pragma unroll
        for (int ks = 0; ks < 4; ++ks) {
            const uint32_t off = (wid * 16 + rowA) * 144 + (ks * 16 + kcA) * 2;
            ldmA(aQh[ks], smb + off);
            ldmA(aQl[ks], smb + 18432 + off);
        }
    }

    float oc[8][4];
    #pragma unroll
    for (int f = 0; f < 8; ++f)
        #pragma unroll
        for (int e = 0; e < 4; ++e) oc[f][e] = 0.f;
    float mrow0 = -1e30f, mrow1 = -1e30f, lrow0 = 0.f, lrow1 = 0.f;

    const uint32_t krow  = (lane & 7) + ((lane >> 4) & 1) * 8;  // K b-frag rows
    const uint32_t kboff = ((lane >> 3) & 1) * 16;
    const int krB = (lane & 7) + ((lane >> 3) & 1) * 8;         // V b-frag rows
    const int ncB = (lane >> 4) * 8;

    for (int kt = 0; kt < 32; ++kt) {
        const int buf = kt % 3;
        if (kt < 31)
            asm volatile("cp.async.wait_group 1;" ::: "memory");
        else
            asm volatile("cp.async.wait_group 0;" ::: "memory");
        __syncthreads();
        if (kt + 2 < 32)
            kv_load(smb, (kt + 2) % 3, gKh, gKl, gVh, gVl, kt + 2, tid);

        const uint32_t KH = smb + 36864 + buf * 36864;
        const uint32_t KL = KH + 9216;
        const uint32_t VH = KH + 18432;
        const uint32_t VL = KH + 27648;

        // ---- S = Q K^T (3-term split) ----
        float sc[8][4];
        #pragma unroll
        for (int f = 0; f < 8; ++f)
            #pragma unroll
            for (int e = 0; e < 4; ++e) sc[f][e] = 0.f;

        #pragma unroll
        for (int ks = 0; ks < 4; ++ks) {
            #pragma unroll
            for (int g = 0; g < 4; ++g) {
                uint32_t th[4], tl[4];
                const uint32_t off = (g * 16 + krow) * 144 + ks * 32 + kboff;
                ldmA(th, KH + off);
                ldmA(tl, KL + off);
                uint32_t b0h[2] = { th[0], th[1] }, b1h[2] = { th[2], th[3] };
                uint32_t b0l[2] = { tl[0], tl[1] }, b1l[2] = { tl[2], tl[3] };
                mma_bf16(sc[2*g],   aQh[ks], b0h);
                mma_bf16(sc[2*g],   aQh[ks], b0l);
                mma_bf16(sc[2*g],   aQl[ks], b0h);
                mma_bf16(sc[2*g+1], aQh[ks], b1h);
                mma_bf16(sc[2*g+1], aQh[ks], b1l);
                mma_bf16(sc[2*g+1], aQl[ks], b1h);
            }
        }

        // ---- online softmax (rows live inside a quad) ----
        float mn0 = -1e30f, mn1 = -1e30f;
        #pragma unroll
        for (int f = 0; f < 8; ++f) {
            mn0 = fmaxf(mn0, fmaxf(sc[f][0], sc[f][1]));
            mn1 = fmaxf(mn1, fmaxf(sc[f][2], sc[f][3]));
        }
        mn0 = fmaxf(mn0, __shfl_xor_sync(0xffffffffu, mn0, 1));
        mn0 = fmaxf(mn0, __shfl_xor_sync(0xffffffffu, mn0, 2));
        mn1 = fmaxf(mn1, __shfl_xor_sync(0xffffffffu, mn1, 1));
        mn1 = fmaxf(mn1, __shfl_xor_sync(0xffffffffu, mn1, 2));
        const float M0 = fmaxf(mrow0, mn0), M1 = fmaxf(mrow1, mn1);
        const float c0 = __expf(mrow0 - M0), c1 = __expf(mrow1 - M1);
        float rs0 = 0.f, rs1 = 0.f;
        #pragma unroll
        for (int f = 0; f < 8; ++f) {
            sc[f][0] = __expf(sc[f][0] - M0); rs0 += sc[f][0];
            sc[f][1] = __expf(sc[f][1] - M0); rs0 += sc[f][1];
            sc[f][2] = __expf(sc[f][2] - M1); rs1 += sc[f][2];
            sc[f][3] = __expf(sc[f][3] - M1); rs1 += sc[f][3];
        }
        rs0 += __shfl_xor_sync(0xffffffffu, rs0, 1);
        rs0 += __shfl_xor_sync(0xffffffffu, rs0, 2);
        rs1 += __shfl_xor_sync(0xffffffffu, rs1, 1);
        rs1 += __shfl_xor_sync(0xffffffffu, rs1, 2);
        lrow0 = lrow0 * c0 + rs0;
        lrow1 = lrow1 * c1 + rs1;
        mrow0 = M0; mrow1 = M1;
        #pragma unroll
        for (int f = 0; f < 8; ++f) {
            oc[f][0] *= c0; oc[f][1] *= c0;
            oc[f][2] *= c1; oc[f][3] *= c1;
        }

        // ---- pack P fragments (C-frag -> A-frag layout, in registers) ----
        uint32_t aPh[4][4], aPl[4][4];
        #pragma unroll
        for (int ks = 0; ks < 4; ++ks) {
            const int f0 = 2 * ks, f1 = 2 * ks + 1;
            splitpair(sc[f0][0], sc[f0][1], aPh[ks][0], aPl[ks][0]);
            splitpair(sc[f0][2], sc[f0][3], aPh[ks][1], aPl[ks][1]);
            splitpair(sc[f1][0], sc[f1][1], aPh[ks][2], aPl[ks][2]);
            splitpair(sc[f1][2], sc[f1][3], aPh[ks][3], aPl[ks][3]);
        }

        // ---- O += P V (3-term split) ----
        #pragma unroll
        for (int ks = 0; ks < 4; ++ks) {
            #pragma unroll
            for (int g = 0; g < 4; ++g) {
                uint32_t th[4], tl[4];
                const uint32_t off = (ks * 16 + krB) * 144 + (g * 16 + ncB) * 2;
                ldmBT(th, VH + off);
                ldmBT(tl, VL + off);
                uint32_t b0h[2] = { th[0], th[1] }, b1h[2] = { th[2], th[3] };
                uint32_t b0l[2] = { tl[0], tl[1] }, b1l[2] = { tl[2], tl[3] };
                mma_bf16(oc[2*g],   aPh[ks], b0h);
                mma_bf16(oc[2*g],   aPh[ks], b0l);
                mma_bf16(oc[2*g],   aPl[ks], b0h);
                mma_bf16(oc[2*g+1], aPh[ks], b1h);
                mma_bf16(oc[2*g+1], aPh[ks], b1l);
                mma_bf16(oc[2*g+1], aPl[ks], b1h);
            }
        }
    }

    // ---- epilogue: normalize, split, write ctx bf16 hi/lo ----
    const int b = bh >> 4, h = bh & 15;
    const float i0 = 1.0f / lrow0, i1 = 1.0f / lrow1;
    const int lg0 = qt * 128 + wid * 16 + (lane >> 2);
    const int lg1 = lg0 + 8;
    #pragma unroll
    for (int f = 0; f < 8; ++f) {
        const int col = h * 64 + 8 * f + (lane & 3) * 2;
        uint32_t hi, lo;
        splitpair(oc[f][0] * i0, oc[f][1] * i0, hi, lo);
        const size_t idx0 = ((size_t)(b * SEQ + lg0)) * DMODEL + col;
        *(uint32_t*)&g_Cbf[0][idx0] = hi;
        *(uint32_t*)&g_Cbf[1][idx0] = lo;
        splitpair(oc[f][2] * i1, oc[f][3] * i1, hi, lo);
        const size_t idx1 = ((size_t)(b * SEQ + lg1)) * DMODEL + col;
        *(uint32_t*)&g_Cbf[0][idx1] = hi;
        *(uint32_t*)&g_Cbf[1][idx1] = lo;
    }
}

// ---------------------------------------------------------------------------
// Launch.  Inputs: query, key, value, Wq, Wk, Wv, out_w, out_b, coupling
// coupling is (correctly) unused: the Kuramoto phase bias is constant along
// the softmax axis and cancels exactly.
// ---------------------------------------------------------------------------
extern "C" void kernel_launch(void* const* d_in, const int* in_sizes, int n_in,
                              void* d_out, int out_size)
{
    const float* q     = (const float*)d_in[0];
    const float* k     = (const float*)d_in[1];
    const float* v     = (const float*)d_in[2];
    const float* wq    = (const float*)d_in[3];
    const float* wk    = (const float*)d_in[4];
    const float* wv    = (const float*)d_in[5];
    const float* out_w = (const float*)d_in[6];
    const float* out_b = (const float*)d_in[7];
    float* out = (float*)d_out;

    // bf16 hi/lo splits of inputs
    convert_act_kernel<<<dim3(512, 3), 256>>>(q, k, v);
    convert_w_kernel<<<dim3(256, 3), 256>>>(wq, wk, wv);
    convert_outw_kernel<<<512, 256>>>(out_w);

    // QKV projection -> bf16 Q/K/V (Q pre-scaled)
    cudaFuncSetAttribute(gemm_qkv_bf16,
                         cudaFuncAttributeMaxDynamicSharedMemorySize, GSMEM);
    gemm_qkv_bf16<<<dim3(8, 32, 3), 256, GSMEM>>>();

    // tensor-core flash attention -> ctx bf16 hi/lo
    cudaFuncSetAttribute(attn_mma_kernel,
                         cudaFuncAttributeMaxDynamicSharedMemorySize, ATT_SMEM);
    attn_mma_kernel<<<dim3(SEQ / 128, BATCH * NHEADS), 256, ATT_SMEM>>>();

    // output projection
    cudaFuncSetAttribute(gemm_out_bf16,
                         cudaFuncAttributeMaxDynamicSharedMemorySize, GSMEM);
    gemm_out_bf16<<<dim3(8, 32), 256, GSMEM>>>(out_b, out);
}

// round 11
// speedup vs baseline: 3.3214x; 1.0907x over previous
#include <cuda_runtime.h>
#include <cuda_bf16.h>
#include <cstdint>

// Problem constants
#define BATCH 2
#define SEQ   2048
#define DMODEL 1024
#define NHEADS 16
#define DK    64
#define BL    (BATCH*SEQ)          // 4096 rows

// bf16 split operands (ver 0 = hi, ver 1 = lo)
__device__ __align__(16) __nv_bfloat16 g_Abf[3][2][BL*DMODEL];      // q/k/v acts
__device__ __align__(16) __nv_bfloat16 g_Wbf[3][2][DMODEL*DMODEL];  // W packed [d][h*64+kc]
__device__ __align__(16) __nv_bfloat16 g_Wobf[2][DMODEL*DMODEL];    // out_w [d][n]
__device__ __align__(16) __nv_bfloat16 g_Cbf[2][BL*DMODEL];         // ctx hi/lo
// projected Q/K/V in bf16 hi/lo, [b,h,l,dk]; Q pre-scaled by 0.125
__device__ __align__(16) __nv_bfloat16 g_QKVbf[3][2][BATCH*NHEADS*SEQ*DK];

// ---------------------------------------------------------------------------
// PTX helpers (all plain sm_80-class)
// ---------------------------------------------------------------------------
__device__ __forceinline__ uint32_t smem_u32(const void* p) {
    uint32_t a;
    asm("{ .reg .u64 t; cvta.to.shared.u64 t, %1; cvt.u32.u64 %0, t; }"
        : "=r"(a) : "l"(p));
    return a;
}
#define CP16(s, g) \
    asm volatile("cp.async.cg.shared.global [%0], [%1], 16;" :: "r"(s), "l"(g) : "memory")
#define CP_COMMIT() asm volatile("cp.async.commit_group;" ::: "memory")

__device__ __forceinline__ void ldmA(uint32_t r[4], uint32_t addr) {
    asm volatile("ldmatrix.sync.aligned.m8n8.x4.shared.b16 {%0,%1,%2,%3}, [%4];"
                 : "=r"(r[0]), "=r"(r[1]), "=r"(r[2]), "=r"(r[3]) : "r"(addr));
}
__device__ __forceinline__ void ldmBT(uint32_t r[4], uint32_t addr) {
    asm volatile("ldmatrix.sync.aligned.m8n8.x4.trans.shared.b16 {%0,%1,%2,%3}, [%4];"
                 : "=r"(r[0]), "=r"(r[1]), "=r"(r[2]), "=r"(r[3]) : "r"(addr));
}
__device__ __forceinline__ void mma_bf16(float c[4], const uint32_t a[4],
                                         const uint32_t b[2]) {
    asm volatile("mma.sync.aligned.m16n8k16.row.col.f32.bf16.bf16.f32 "
                 "{%0,%1,%2,%3}, {%4,%5,%6,%7}, {%8,%9}, {%0,%1,%2,%3};"
                 : "+f"(c[0]), "+f"(c[1]), "+f"(c[2]), "+f"(c[3])
                 : "r"(a[0]), "r"(a[1]), "r"(a[2]), "r"(a[3]),
                   "r"(b[0]), "r"(b[1]));
}

// ---------------------------------------------------------------------------
// bf16 hi/lo split helpers
// ---------------------------------------------------------------------------
__device__ __forceinline__ void split1(float x, __nv_bfloat16& h, __nv_bfloat16& l) {
    h = __float2bfloat16(x);
    l = __float2bfloat16(x - __bfloat162float(h));
}
__device__ __forceinline__ void splitpair(float x0, float x1,
                                          uint32_t& hi, uint32_t& lo) {
    __nv_bfloat16 h0, l0, h1, l1;
    split1(x0, h0, l0);
    split1(x1, h1, l1);
    hi = (uint32_t)__bfloat16_as_ushort(h0)
       | ((uint32_t)__bfloat16_as_ushort(h1) << 16);
    lo = (uint32_t)__bfloat16_as_ushort(l0)
       | ((uint32_t)__bfloat16_as_ushort(l1) << 16);
}

// ---------------------------------------------------------------------------
// input conversions
// ---------------------------------------------------------------------------
__global__ void convert_act_kernel(const float* __restrict__ q,
                                   const float* __restrict__ k,
                                   const float* __restrict__ v)
{
    const int which = blockIdx.y;
    const float4* src = (const float4*)(which == 0 ? q : which == 1 ? k : v);
    __nv_bfloat16* hi = g_Abf[which][0];
    __nv_bfloat16* lo = g_Abf[which][1];
    const int n4 = BL * DMODEL / 4;
    for (int i = blockIdx.x * blockDim.x + threadIdx.x; i < n4;
         i += gridDim.x * blockDim.x) {
        float4 x = src[i];
        __nv_bfloat16 h, l;
        split1(x.x, h, l); hi[4*i+0] = h; lo[4*i+0] = l;
        split1(x.y, h, l); hi[4*i+1] = h; lo[4*i+1] = l;
        split1(x.z, h, l); hi[4*i+2] = h; lo[4*i+2] = l;
        split1(x.w, h, l); hi[4*i+3] = h; lo[4*i+3] = l;
    }
}

// W[h][d][kc] -> g_Wbf[which][ver][d*1024 + h*64 + kc]
__global__ void convert_w_kernel(const float* __restrict__ wq,
                                 const float* __restrict__ wk,
                                 const float* __restrict__ wv)
{
    const int which = blockIdx.y;
    const float4* src = (const float4*)(which == 0 ? wq : which == 1 ? wk : wv);
    const int n4 = DMODEL * DMODEL / 4;
    for (int i = blockIdx.x * blockDim.x + threadIdx.x; i < n4;
         i += gridDim.x * blockDim.x) {
        const int flat = i * 4;
        const int h = flat >> 16, d = (flat >> 6) & 1023, kc = flat & 63;
        const int dst = d * DMODEL + h * 64 + kc;
        float4 x = src[i];
        __nv_bfloat16 hh, ll;
        split1(x.x, hh, ll); g_Wbf[which][0][dst+0] = hh; g_Wbf[which][1][dst+0] = ll;
        split1(x.y, hh, ll); g_Wbf[which][0][dst+1] = hh; g_Wbf[which][1][dst+1] = ll;
        split1(x.z, hh, ll); g_Wbf[which][0][dst+2] = hh; g_Wbf[which][1][dst+2] = ll;
        split1(x.w, hh, ll); g_Wbf[which][0][dst+3] = hh; g_Wbf[which][1][dst+3] = ll;
    }
}

__global__ void convert_outw_kernel(const float* __restrict__ src4f)
{
    const float4* src = (const float4*)src4f;
    const int n4 = DMODEL * DMODEL / 4;
    for (int i = blockIdx.x * blockDim.x + threadIdx.x; i < n4;
         i += gridDim.x * blockDim.x) {
        float4 x = src[i];
        __nv_bfloat16 h, l;
        split1(x.x, h, l); g_Wobf[0][4*i+0] = h; g_Wobf[1][4*i+0] = l;
        split1(x.y, h, l); g_Wobf[0][4*i+1] = h; g_Wobf[1][4*i+1] = l;
        split1(x.z, h, l); g_Wobf[0][4*i+2] = h; g_Wobf[1][4*i+2] = l;
        split1(x.w, h, l); g_Wobf[0][4*i+3] = h; g_Wobf[1][4*i+3] = l;
    }
}

// ---------------------------------------------------------------------------
// bf16-split GEMM core: 3-stage cp.async pipeline, ONE sync per stage.
// (unchanged from R10 — validated)
// ---------------------------------------------------------------------------
#define STG_BYTES 37888
#define SM_A(st, ver) ((st) * STG_BYTES + (ver) * 10240)
#define SM_B(st, ver) ((st) * STG_BYTES + 20480 + (ver) * 8704)
#define GSMEM (3 * STG_BYTES)   // 113664

__device__ __forceinline__ void gemm_load_stage(
    uint32_t smb, int st,
    const __nv_bfloat16* __restrict__ gAhi, const __nv_bfloat16* __restrict__ gAlo,
    const __nv_bfloat16* __restrict__ gBhi, const __nv_bfloat16* __restrict__ gBlo,
    int m0, int n0, int k0, int tid)
{
    #pragma unroll
    for (int j = 0; j < 4; ++j) {
        const int idx = tid + 256 * j;
        const int ver = idx >> 9, r = idx & 511;
        const int row = r >> 2, c16 = r & 3;
        const __nv_bfloat16* src = (ver ? gAlo : gAhi)
            + (size_t)(m0 + row) * DMODEL + k0 + c16 * 8;
        CP16(smb + SM_A(st, ver) + row * 80 + c16 * 16, src);
    }
    #pragma unroll
    for (int j = 0; j < 4; ++j) {
        const int idx = tid + 256 * j;
        const int ver = idx >> 9, r = idx & 511;
        const int krow = r >> 4, c16 = r & 15;
        const __nv_bfloat16* src = (ver ? gBlo : gBhi)
            + (size_t)(k0 + krow) * DMODEL + n0 + c16 * 8;
        CP16(smb + SM_B(st, ver) + krow * 272 + c16 * 16, src);
    }
    CP_COMMIT();
}

__device__ __forceinline__ void gemm_compute_stage(
    uint32_t smb, int st, float acc[4][4][4], int wm, int wn, int lane)
{
    const int rowA = (lane & 7) + ((lane >> 3) & 1) * 8;
    const int kcA  = (lane >> 4) * 8;
    const int baseA = rowA * 80 + kcA * 2;
    const int krB = (lane & 7) + ((lane >> 3) & 1) * 8;
    const int ncB = (lane >> 4) * 8;

    #pragma unroll
    for (int ks = 0; ks < 2; ++ks) {
        uint32_t ahi[4][4], alo[4][4], bhi[4][2], blo[4][2];
        #pragma unroll
        for (int m = 0; m < 4; ++m) {
            const uint32_t off = (wm + m * 16) * 80 + ks * 32 + baseA;
            ldmA(ahi[m], smb + SM_A(st, 0) + off);
            ldmA(alo[m], smb + SM_A(st, 1) + off);
        }
        #pragma unroll
        for (int np = 0; np < 2; ++np) {
            const uint32_t off = (ks * 16 + krB) * 272 + (wn + np * 16 + ncB) * 2;
            uint32_t t[4];
            ldmBT(t, smb + SM_B(st, 0) + off);
            bhi[2*np][0] = t[0]; bhi[2*np][1] = t[1];
            bhi[2*np+1][0] = t[2]; bhi[2*np+1][1] = t[3];
            ldmBT(t, smb + SM_B(st, 1) + off);
            blo[2*np][0] = t[0]; blo[2*np][1] = t[1];
            blo[2*np+1][0] = t[2]; blo[2*np+1][1] = t[3];
        }
        #pragma unroll
        for (int m = 0; m < 4; ++m)
            #pragma unroll
            for (int n = 0; n < 4; ++n) {
                mma_bf16(acc[m][n], ahi[m], bhi[n]);
                mma_bf16(acc[m][n], ahi[m], blo[n]);
                mma_bf16(acc[m][n], alo[m], bhi[n]);
            }
    }
}

__device__ __forceinline__ void gemm_mainloop(
    uint32_t smb, float acc[4][4][4],
    const __nv_bfloat16* gAhi, const __nv_bfloat16* gAlo,
    const __nv_bfloat16* gBhi, const __nv_bfloat16* gBlo,
    int m0, int n0, int tid, int wm, int wn, int lane)
{
    gemm_load_stage(smb, 0, gAhi, gAlo, gBhi, gBlo, m0, n0, 0, tid);
    gemm_load_stage(smb, 1, gAhi, gAlo, gBhi, gBlo, m0, n0, 32, tid);
    for (int s = 0; s < 32; ++s) {
        if (s < 31)
            asm volatile("cp.async.wait_group 1;" ::: "memory");
        else
            asm volatile("cp.async.wait_group 0;" ::: "memory");
        __syncthreads();
        if (s + 2 < 32)
            gemm_load_stage(smb, (s + 2) % 3, gAhi, gAlo, gBhi, gBlo,
                            m0, n0, (s + 2) * 32, tid);
        gemm_compute_stage(smb, s % 3, acc, wm, wn, lane);
    }
}

// ---------------------------------------------------------------------------
// QKV projection: writes bf16 hi/lo Q/K/V directly (Q scaled by 0.125)
// ---------------------------------------------------------------------------
__global__ __launch_bounds__(256, 2)
void gemm_qkv_bf16()
{
    extern __shared__ char sm[];
    const uint32_t smb = smem_u32(sm);
    const int tid = threadIdx.x, lane = tid & 31, warp = tid >> 5;
    const int wm = (warp >> 2) * 64, wn = (warp & 3) * 32;
    const int which = blockIdx.z;
    const int m0 = blockIdx.y * 128, n0 = blockIdx.x * 128;
    __nv_bfloat16* Ch = g_QKVbf[which][0];
    __nv_bfloat16* Cl = g_QKVbf[which][1];
    const float qs = (which == 0) ? 0.125f : 1.0f;

    float acc[4][4][4];
    #pragma unroll
    for (int m = 0; m < 4; ++m)
        #pragma unroll
        for (int n = 0; n < 4; ++n)
            #pragma unroll
            for (int e = 0; e < 4; ++e) acc[m][n][e] = 0.f;

    gemm_mainloop(smb, acc, g_Abf[which][0], g_Abf[which][1],
                  g_Wbf[which][0], g_Wbf[which][1], m0, n0, tid, wm, wn, lane);

    #pragma unroll
    for (int m = 0; m < 4; ++m) {
        const int r0 = m0 + wm + m * 16 + (lane >> 2);
        #pragma unroll
        for (int n = 0; n < 4; ++n) {
            const int col = n0 + wn + n * 8 + (lane & 3) * 2;
            const int h = col >> 6, kc = col & 63;
            uint32_t hi, lo;
            {
                const int b = r0 >> 11, l = r0 & 2047;
                const size_t idx = (((size_t)(b * NHEADS + h) * SEQ) + l) * DK + kc;
                splitpair(acc[m][n][0] * qs, acc[m][n][1] * qs, hi, lo);
                *(uint32_t*)&Ch[idx] = hi;
                *(uint32_t*)&Cl[idx] = lo;
            }
            {
                const int r1 = r0 + 8;
                const int b = r1 >> 11, l = r1 & 2047;
                const size_t idx = (((size_t)(b * NHEADS + h) * SEQ) + l) * DK + kc;
                splitpair(acc[m][n][2] * qs, acc[m][n][3] * qs, hi, lo);
                *(uint32_t*)&Ch[idx] = hi;
                *(uint32_t*)&Cl[idx] = lo;
            }
        }
    }
}

// ---------------------------------------------------------------------------
// Output projection
// ---------------------------------------------------------------------------
__global__ __launch_bounds__(256, 2)
void gemm_out_bf16(const float* __restrict__ out_b, float* __restrict__ out)
{
    extern __shared__ char sm[];
    const uint32_t smb = smem_u32(sm);
    const int tid = threadIdx.x, lane = tid & 31, warp = tid >> 5;
    const int wm = (warp >> 2) * 64, wn = (warp & 3) * 32;
    const int m0 = blockIdx.y * 128, n0 = blockIdx.x * 128;

    float acc[4][4][4];
    #pragma unroll
    for (int m = 0; m < 4; ++m)
        #pragma unroll
        for (int n = 0; n < 4; ++n)
            #pragma unroll
            for (int e = 0; e < 4; ++e) acc[m][n][e] = 0.f;

    gemm_mainloop(smb, acc, g_Cbf[0], g_Cbf[1], g_Wobf[0], g_Wobf[1],
                  m0, n0, tid, wm, wn, lane);

    #pragma unroll
    for (int m = 0; m < 4; ++m) {
        const int r0 = m0 + wm + m * 16 + (lane >> 2);
        #pragma unroll
        for (int n = 0; n < 4; ++n) {
            const int col = n0 + wn + n * 8 + (lane & 3) * 2;
            const float b0 = out_b[col], b1 = out_b[col + 1];
            float2 v0 = { acc[m][n][0] + b0, acc[m][n][1] + b1 };
            float2 v1 = { acc[m][n][2] + b0, acc[m][n][3] + b1 };
            *(float2*)&out[(size_t)r0 * DMODEL + col] = v0;
            *(float2*)&out[(size_t)(r0 + 8) * DMODEL + col] = v1;
        }
    }
}

// ---------------------------------------------------------------------------
// Tensor-core flash attention.  CTA = 128 q-rows, 4 warps x 32 rows (2 m-frags
// per warp) — halves per-q-row ldmatrix traffic vs 16-row warps, since a warp
// reads K/V once regardless of how many q-rows it owns.  2-stage KV ring,
// 110592 B smem -> 2 CTAs/SM.  Fragment math identical to the validated R10
// kernel with an added mi loop.  Phase bias cancels in softmax.
// ---------------------------------------------------------------------------
#define ATT_SMEM (36864 + 2 * 36864)   // 110592

__device__ __forceinline__ void kv_load(
    uint32_t smb, int buf,
    const __nv_bfloat16* kh, const __nv_bfloat16* kl,
    const __nv_bfloat16* vh, const __nv_bfloat16* vl,
    int kt, int tid)
{
    const uint32_t base = smb + 36864 + buf * 36864;
    const size_t goff = (size_t)kt * 64 * DK;
    #pragma unroll
    for (int j = 0; j < 16; ++j) {
        const int idx = tid + 128 * j;
        const int sel = idx >> 9, r = idx & 511;
        const int row = r >> 3, c16 = r & 7;
        const __nv_bfloat16* src =
            (sel == 0 ? kh : sel == 1 ? kl : sel == 2 ? vh : vl)
            + goff + row * DK + c16 * 8;
        CP16(base + sel * 9216 + row * 144 + c16 * 16, src);
    }
    CP_COMMIT();
}

__global__ __launch_bounds__(128)
void attn_mma_kernel()
{
    extern __shared__ char sm[];
    const uint32_t smb = smem_u32(sm);
    const int tid = threadIdx.x, lane = tid & 31, wid = tid >> 5;  // 0..3
    const int qt = blockIdx.x, bh = blockIdx.y;
    const size_t bhoff = (size_t)bh * SEQ * DK;

    const __nv_bfloat16* gQh = g_QKVbf[0][0] + bhoff + (size_t)qt * 128 * DK;
    const __nv_bfloat16* gQl = g_QKVbf[0][1] + bhoff + (size_t)qt * 128 * DK;
    const __nv_bfloat16* gKh = g_QKVbf[1][0] + bhoff;
    const __nv_bfloat16* gKl = g_QKVbf[1][1] + bhoff;
    const __nv_bfloat16* gVh = g_QKVbf[2][0] + bhoff;
    const __nv_bfloat16* gVl = g_QKVbf[2][1] + bhoff;

    // Q tile load (group 0): 2 ver x 128 rows x 8 chunks = 2048
    #pragma unroll
    for (int j = 0; j < 16; ++j) {
        const int idx = tid + 128 * j;
        const int ver = idx >> 10, r = idx & 1023;
        const int row = r >> 3, c16 = r & 7;
        CP16(smb + ver * 18432 + row * 144 + c16 * 16,
             (ver ? gQl : gQh) + row * DK + c16 * 8);
    }
    CP_COMMIT();
    kv_load(smb, 0, gKh, gKl, gVh, gVl, 0, tid);   // group 1

    asm volatile("cp.async.wait_group 1;" ::: "memory");  // Q ready
    __syncthreads();

    // Q fragments (2 m-frags x 4 ks, hi+lo) held for the whole kernel
    uint32_t aQh[2][4][4], aQl[2][4][4];
    {
        const int rowA = (lane & 7) + ((lane >> 3) & 1) * 8;
        const int kcA  = (lane >> 4) * 8;
        #pragma unroll
        for (int mi = 0; mi < 2; ++mi)
            #pragma unroll
            for (int ks = 0; ks < 4; ++ks) {
                const uint32_t off =
                    (wid * 32 + mi * 16 + rowA) * 144 + (ks * 16 + kcA) * 2;
                ldmA(aQh[mi][ks], smb + off);
                ldmA(aQl[mi][ks], smb + 18432 + off);
            }
    }

    float oc[2][8][4];
    #pragma unroll
    for (int mi = 0; mi < 2; ++mi)
        #pragma unroll
        for (int f = 0; f < 8; ++f)
            #pragma unroll
            for (int e = 0; e < 4; ++e) oc[mi][f][e] = 0.f;
    float mrow[2][2], lrow[2][2];
    #pragma unroll
    for (int mi = 0; mi < 2; ++mi) {
        mrow[mi][0] = -1e30f; mrow[mi][1] = -1e30f;
        lrow[mi][0] = 0.f;    lrow[mi][1] = 0.f;
    }

    const uint32_t krow  = (lane & 7) + ((lane >> 4) & 1) * 8;  // K b-frag rows
    const uint32_t kboff = ((lane >> 3) & 1) * 16;
    const int krB = (lane & 7) + ((lane >> 3) & 1) * 8;         // V b-frag rows
    const int ncB = (lane >> 4) * 8;

    for (int kt = 0; kt < 32; ++kt) {
        const int buf = kt & 1;
        if (kt < 31) {
            kv_load(smb, buf ^ 1, gKh, gKl, gVh, gVl, kt + 1, tid);
            asm volatile("cp.async.wait_group 1;" ::: "memory");
        } else {
            asm volatile("cp.async.wait_group 0;" ::: "memory");
        }
        __syncthreads();

        const uint32_t KH = smb + 36864 + buf * 36864;
        const uint32_t KL = KH + 9216;
        const uint32_t VH = KH + 18432;
        const uint32_t VL = KH + 27648;

        // ---- S = Q K^T (3-term split), 2 m-frags share each K fragment ----
        float sc[2][8][4];
        #pragma unroll
        for (int mi = 0; mi < 2; ++mi)
            #pragma unroll
            for (int f = 0; f < 8; ++f)
                #pragma unroll
                for (int e = 0; e < 4; ++e) sc[mi][f][e] = 0.f;

        #pragma unroll
        for (int ks = 0; ks < 4; ++ks) {
            #pragma unroll
            for (int g = 0; g < 4; ++g) {
                uint32_t th[4], tl[4];
                const uint32_t off = (g * 16 + krow) * 144 + ks * 32 + kboff;
                ldmA(th, KH + off);
                ldmA(tl, KL + off);
                uint32_t b0h[2] = { th[0], th[1] }, b1h[2] = { th[2], th[3] };
                uint32_t b0l[2] = { tl[0], tl[1] }, b1l[2] = { tl[2], tl[3] };
                #pragma unroll
                for (int mi = 0; mi < 2; ++mi) {
                    mma_bf16(sc[mi][2*g],   aQh[mi][ks], b0h);
                    mma_bf16(sc[mi][2*g],   aQh[mi][ks], b0l);
                    mma_bf16(sc[mi][2*g],   aQl[mi][ks], b0h);
                    mma_bf16(sc[mi][2*g+1], aQh[mi][ks], b1h);
                    mma_bf16(sc[mi][2*g+1], aQh[mi][ks], b1l);
                    mma_bf16(sc[mi][2*g+1], aQl[mi][ks], b1h);
                }
            }
        }

        // ---- online softmax + P pack, per m-frag ----
        uint32_t aPh[2][4][4], aPl[2][4][4];
        #pragma unroll
        for (int mi = 0; mi < 2; ++mi) {
            float mn0 = -1e30f, mn1 = -1e30f;
            #pragma unroll
            for (int f = 0; f < 8; ++f) {
                mn0 = fmaxf(mn0, fmaxf(sc[mi][f][0], sc[mi][f][1]));
                mn1 = fmaxf(mn1, fmaxf(sc[mi][f][2], sc[mi][f][3]));
            }
            mn0 = fmaxf(mn0, __shfl_xor_sync(0xffffffffu, mn0, 1));
            mn0 = fmaxf(mn0, __shfl_xor_sync(0xffffffffu, mn0, 2));
            mn1 = fmaxf(mn1, __shfl_xor_sync(0xffffffffu, mn1, 1));
            mn1 = fmaxf(mn1, __shfl_xor_sync(0xffffffffu, mn1, 2));
            const float M0 = fmaxf(mrow[mi][0], mn0);
            const float M1 = fmaxf(mrow[mi][1], mn1);
            const float c0 = __expf(mrow[mi][0] - M0);
            const float c1 = __expf(mrow[mi][1] - M1);
            float rs0 = 0.f, rs1 = 0.f;
            #pragma unroll
            for (int f = 0; f < 8; ++f) {
                sc[mi][f][0] = __expf(sc[mi][f][0] - M0); rs0 += sc[mi][f][0];
                sc[mi][f][1] = __expf(sc[mi][f][1] - M0); rs0 += sc[mi][f][1];
                sc[mi][f][2] = __expf(sc[mi][f][2] - M1); rs1 += sc[mi][f][2];
                sc[mi][f][3] = __expf(sc[mi][f][3] - M1); rs1 += sc[mi][f][3];
            }
            rs0 += __shfl_xor_sync(0xffffffffu, rs0, 1);
            rs0 += __shfl_xor_sync(0xffffffffu, rs0, 2);
            rs1 += __shfl_xor_sync(0xffffffffu, rs1, 1);
            rs1 += __shfl_xor_sync(0xffffffffu, rs1, 2);
            lrow[mi][0] = lrow[mi][0] * c0 + rs0;
            lrow[mi][1] = lrow[mi][1] * c1 + rs1;
            mrow[mi][0] = M0; mrow[mi][1] = M1;
            #pragma unroll
            for (int f = 0; f < 8; ++f) {
                oc[mi][f][0] *= c0; oc[mi][f][1] *= c0;
                oc[mi][f][2] *= c1; oc[mi][f][3] *= c1;
            }
            #pragma unroll
            for (int ks = 0; ks < 4; ++ks) {
                const int f0 = 2 * ks, f1 = 2 * ks + 1;
                splitpair(sc[mi][f0][0], sc[mi][f0][1], aPh[mi][ks][0], aPl[mi][ks][0]);
                splitpair(sc[mi][f0][2], sc[mi][f0][3], aPh[mi][ks][1], aPl[mi][ks][1]);
                splitpair(sc[mi][f1][0], sc[mi][f1][1], aPh[mi][ks][2], aPl[mi][ks][2]);
                splitpair(sc[mi][f1][2], sc[mi][f1][3], aPh[mi][ks][3], aPl[mi][ks][3]);
            }
        }

        // ---- O += P V (3-term split), 2 m-frags share each V fragment ----
        #pragma unroll
        for (int ks = 0; ks < 4; ++ks) {
            #pragma unroll
            for (int g = 0; g < 4; ++g) {
                uint32_t th[4], tl[4];
                const uint32_t off = (ks * 16 + krB) * 144 + (g * 16 + ncB) * 2;
                ldmBT(th, VH + off);
                ldmBT(tl, VL + off);
                uint32_t b0h[2] = { th[0], th[1] }, b1h[2] = { th[2], th[3] };
                uint32_t b0l[2] = { tl[0], tl[1] }, b1l[2] = { tl[2], tl[3] };
                #pragma unroll
                for (int mi = 0; mi < 2; ++mi) {
                    mma_bf16(oc[mi][2*g],   aPh[mi][ks], b0h);
                    mma_bf16(oc[mi][2*g],   aPh[mi][ks], b0l);
                    mma_bf16(oc[mi][2*g],   aPl[mi][ks], b0h);
                    mma_bf16(oc[mi][2*g+1], aPh[mi][ks], b1h);
                    mma_bf16(oc[mi][2*g+1], aPh[mi][ks], b1l);
                    mma_bf16(oc[mi][2*g+1], aPl[mi][ks], b1h);
                }
            }
        }
    }

    // ---- epilogue: normalize, split, write ctx bf16 hi/lo ----
    const int b = bh >> 4, h = bh & 15;
    #pragma unroll
    for (int mi = 0; mi < 2; ++mi) {
        const float i0 = 1.0f / lrow[mi][0], i1 = 1.0f / lrow[mi][1];
        const int lg0 = qt * 128 + wid * 32 + mi * 16 + (lane >> 2);
        const int lg1 = lg0 + 8;
        #pragma unroll
        for (int f = 0; f < 8; ++f) {
            const int col = h * 64 + 8 * f + (lane & 3) * 2;
            uint32_t hi, lo;
            splitpair(oc[mi][f][0] * i0, oc[mi][f][1] * i0, hi, lo);
            const size_t idx0 = ((size_t)(b * SEQ + lg0)) * DMODEL + col;
            *(uint32_t*)&g_Cbf[0][idx0] = hi;
            *(uint32_t*)&g_Cbf[1][idx0] = lo;
            splitpair(oc[mi][f][2] * i1, oc[mi][f][3] * i1, hi, lo);
            const size_t idx1 = ((size_t)(b * SEQ + lg1)) * DMODEL + col;
            *(uint32_t*)&g_Cbf[0][idx1] = hi;
            *(uint32_t*)&g_Cbf[1][idx1] = lo;
        }
    }
}

// ---------------------------------------------------------------------------
// Launch.  Inputs: query, key, value, Wq, Wk, Wv, out_w, out_b, coupling
// coupling is (correctly) unused: the Kuramoto phase bias is constant along
// the softmax axis and cancels exactly.
// ---------------------------------------------------------------------------
extern "C" void kernel_launch(void* const* d_in, const int* in_sizes, int n_in,
                              void* d_out, int out_size)
{
    const float* q     = (const float*)d_in[0];
    const float* k     = (const float*)d_in[1];
    const float* v     = (const float*)d_in[2];
    const float* wq    = (const float*)d_in[3];
    const float* wk    = (const float*)d_in[4];
    const float* wv    = (const float*)d_in[5];
    const float* out_w = (const float*)d_in[6];
    const float* out_b = (const float*)d_in[7];
    float* out = (float*)d_out;

    // bf16 hi/lo splits of inputs
    convert_act_kernel<<<dim3(512, 3), 256>>>(q, k, v);
    convert_w_kernel<<<dim3(256, 3), 256>>>(wq, wk, wv);
    convert_outw_kernel<<<512, 256>>>(out_w);

    // QKV projection -> bf16 Q/K/V (Q pre-scaled)
    cudaFuncSetAttribute(gemm_qkv_bf16,
                         cudaFuncAttributeMaxDynamicSharedMemorySize, GSMEM);
    gemm_qkv_bf16<<<dim3(8, 32, 3), 256, GSMEM>>>();

    // tensor-core flash attention -> ctx bf16 hi/lo
    cudaFuncSetAttribute(attn_mma_kernel,
                         cudaFuncAttributeMaxDynamicSharedMemorySize, ATT_SMEM);
    attn_mma_kernel<<<dim3(SEQ / 128, BATCH * NHEADS), 128, ATT_SMEM>>>();

    // output projection
    cudaFuncSetAttribute(gemm_out_bf16,
                         cudaFuncAttributeMaxDynamicSharedMemorySize, GSMEM);
    gemm_out_bf16<<<dim3(8, 32), 256, GSMEM>>>(out_b, out);
}

// round 17
// speedup vs baseline: 3.7128x; 1.1178x over previous
#include <cuda_runtime.h>
#include <cuda_bf16.h>
#include <cstdint>

// Problem constants
#define BATCH 2
#define SEQ   2048
#define DMODEL 1024
#define NHEADS 16
#define DK    64
#define BL    (BATCH*SEQ)          // 4096 rows

// bf16 split operands (ver 0 = hi, ver 1 = lo)
__device__ __align__(16) __nv_bfloat16 g_Abf[3][2][BL*DMODEL];      // q/k/v acts
__device__ __align__(16) __nv_bfloat16 g_Wbf[3][2][DMODEL*DMODEL];  // W packed [d][h*64+kc]
__device__ __align__(16) __nv_bfloat16 g_Wobf[2][DMODEL*DMODEL];    // out_w [d][n]
__device__ __align__(16) __nv_bfloat16 g_Cbf[2][BL*DMODEL];         // ctx hi/lo
// projected Q/K/V in bf16 hi/lo, [b,h,l,dk]; Q pre-scaled by 0.125
__device__ __align__(16) __nv_bfloat16 g_QKVbf[3][2][BATCH*NHEADS*SEQ*DK];

// ---------------------------------------------------------------------------
// PTX helpers (all plain sm_80-class)
// ---------------------------------------------------------------------------
__device__ __forceinline__ uint32_t smem_u32(const void* p) {
    uint32_t a;
    asm("{ .reg .u64 t; cvta.to.shared.u64 t, %1; cvt.u32.u64 %0, t; }"
        : "=r"(a) : "l"(p));
    return a;
}
#define CP16(s, g) \
    asm volatile("cp.async.cg.shared.global [%0], [%1], 16;" :: "r"(s), "l"(g) : "memory")
#define CP_COMMIT() asm volatile("cp.async.commit_group;" ::: "memory")

__device__ __forceinline__ void ldmA(uint32_t r[4], uint32_t addr) {
    asm volatile("ldmatrix.sync.aligned.m8n8.x4.shared.b16 {%0,%1,%2,%3}, [%4];"
                 : "=r"(r[0]), "=r"(r[1]), "=r"(r[2]), "=r"(r[3]) : "r"(addr));
}
__device__ __forceinline__ void ldmBT(uint32_t r[4], uint32_t addr) {
    asm volatile("ldmatrix.sync.aligned.m8n8.x4.trans.shared.b16 {%0,%1,%2,%3}, [%4];"
                 : "=r"(r[0]), "=r"(r[1]), "=r"(r[2]), "=r"(r[3]) : "r"(addr));
}
__device__ __forceinline__ void mma_bf16(float c[4], const uint32_t a[4],
                                         const uint32_t b[2]) {
    asm volatile("mma.sync.aligned.m16n8k16.row.col.f32.bf16.bf16.f32 "
                 "{%0,%1,%2,%3}, {%4,%5,%6,%7}, {%8,%9}, {%0,%1,%2,%3};"
                 : "+f"(c[0]), "+f"(c[1]), "+f"(c[2]), "+f"(c[3])
                 : "r"(a[0]), "r"(a[1]), "r"(a[2]), "r"(a[3]),
                   "r"(b[0]), "r"(b[1]));
}

// ---------------------------------------------------------------------------
// bf16 hi/lo split helpers
// ---------------------------------------------------------------------------
__device__ __forceinline__ void split1(float x, __nv_bfloat16& h, __nv_bfloat16& l) {
    h = __float2bfloat16(x);
    l = __float2bfloat16(x - __bfloat162float(h));
}
__device__ __forceinline__ void splitpair(float x0, float x1,
                                          uint32_t& hi, uint32_t& lo) {
    __nv_bfloat16 h0, l0, h1, l1;
    split1(x0, h0, l0);
    split1(x1, h1, l1);
    hi = (uint32_t)__bfloat16_as_ushort(h0)
       | ((uint32_t)__bfloat16_as_ushort(h1) << 16);
    lo = (uint32_t)__bfloat16_as_ushort(l0)
       | ((uint32_t)__bfloat16_as_ushort(l1) << 16);
}
// split float4 -> packed uint2 hi and uint2 lo (8B each)
__device__ __forceinline__ void split4(float4 x, uint2& hi, uint2& lo) {
    splitpair(x.x, x.y, hi.x, lo.x);
    splitpair(x.z, x.w, hi.y, lo.y);
}

// ---------------------------------------------------------------------------
// merged input conversions (one launch; grid.y = role), vectorized stores
//   role 0-2: activations q/k/v   role 3-5: Wq/Wk/Wv   role 6: out_w
// ---------------------------------------------------------------------------
__global__ void convert_all_kernel(const float* __restrict__ q,
                                   const float* __restrict__ k,
                                   const float* __restrict__ v,
                                   const float* __restrict__ wq,
                                   const float* __restrict__ wk,
                                   const float* __restrict__ wv,
                                   const float* __restrict__ out_w)
{
    const int role = blockIdx.y;
    if (role < 3) {
        const float4* src = (const float4*)(role == 0 ? q : role == 1 ? k : v);
        __nv_bfloat16* hi = g_Abf[role][0];
        __nv_bfloat16* lo = g_Abf[role][1];
        const int n4 = BL * DMODEL / 4;
        for (int i = blockIdx.x * blockDim.x + threadIdx.x; i < n4;
             i += gridDim.x * blockDim.x) {
            uint2 h, l;
            split4(src[i], h, l);
            *(uint2*)&hi[4*i] = h;
            *(uint2*)&lo[4*i] = l;
        }
    } else if (role < 6) {
        const int which = role - 3;
        const float4* src = (const float4*)(which == 0 ? wq : which == 1 ? wk : wv);
        const int n4 = DMODEL * DMODEL / 4;
        for (int i = blockIdx.x * blockDim.x + threadIdx.x; i < n4;
             i += gridDim.x * blockDim.x) {
            const int flat = i * 4;
            const int h = flat >> 16, d = (flat >> 6) & 1023, kc = flat & 63;
            const int dst = d * DMODEL + h * 64 + kc;   // 4-elem aligned
            uint2 hh, ll;
            split4(src[i], hh, ll);
            *(uint2*)&g_Wbf[which][0][dst] = hh;
            *(uint2*)&g_Wbf[which][1][dst] = ll;
        }
    } else {
        const float4* src = (const float4*)out_w;
        const int n4 = DMODEL * DMODEL / 4;
        for (int i = blockIdx.x * blockDim.x + threadIdx.x; i < n4;
             i += gridDim.x * blockDim.x) {
            uint2 h, l;
            split4(src[i], h, l);
            *(uint2*)&g_Wobf[0][4*i] = h;
            *(uint2*)&g_Wobf[1][4*i] = l;
        }
    }
}

// ---------------------------------------------------------------------------
// SMEM stage layout shared by both GEMMs (3-stage ring)
// ---------------------------------------------------------------------------
#define STG_BYTES 37888
#define SM_A(st, ver) ((st) * STG_BYTES + (ver) * 10240)
#define SM_B(st, ver) ((st) * STG_BYTES + 20480 + (ver) * 8704)
#define GSMEM (3 * STG_BYTES)   // 113664

// ===========================================================================
// VALIDATED stage8 core: 8 warps (2x4), warp tile 64x32, 256 threads.
// ===========================================================================
__device__ __forceinline__ void gemm_load_stage8(
    uint32_t smb, int st,
    const __nv_bfloat16* __restrict__ gAhi, const __nv_bfloat16* __restrict__ gAlo,
    const __nv_bfloat16* __restrict__ gBhi, const __nv_bfloat16* __restrict__ gBlo,
    int m0, int n0, int k0, int tid)
{
    #pragma unroll
    for (int j = 0; j < 4; ++j) {
        const int idx = tid + 256 * j;
        const int ver = idx >> 9, r = idx & 511;
        const int row = r >> 2, c16 = r & 3;
        const __nv_bfloat16* src = (ver ? gAlo : gAhi)
            + (size_t)(m0 + row) * DMODEL + k0 + c16 * 8;
        CP16(smb + SM_A(st, ver) + row * 80 + c16 * 16, src);
    }
    #pragma unroll
    for (int j = 0; j < 4; ++j) {
        const int idx = tid + 256 * j;
        const int ver = idx >> 9, r = idx & 511;
        const int krow = r >> 4, c16 = r & 15;
        const __nv_bfloat16* src = (ver ? gBlo : gBhi)
            + (size_t)(k0 + krow) * DMODEL + n0 + c16 * 8;
        CP16(smb + SM_B(st, ver) + krow * 272 + c16 * 16, src);
    }
    CP_COMMIT();
}

__device__ __forceinline__ void gemm_compute_stage8(
    uint32_t smb, int st, float acc[4][4][4], int wm, int wn, int lane)
{
    const int rowA = (lane & 7) + ((lane >> 3) & 1) * 8;
    const int kcA  = (lane >> 4) * 8;
    const int baseA = rowA * 80 + kcA * 2;
    const int krB = (lane & 7) + ((lane >> 3) & 1) * 8;
    const int ncB = (lane >> 4) * 8;

    #pragma unroll
    for (int ks = 0; ks < 2; ++ks) {
        uint32_t ahi[4][4], alo[4][4], bhi[4][2], blo[4][2];
        #pragma unroll
        for (int m = 0; m < 4; ++m) {
            const uint32_t off = (wm + m * 16) * 80 + ks * 32 + baseA;
            ldmA(ahi[m], smb + SM_A(st, 0) + off);
            ldmA(alo[m], smb + SM_A(st, 1) + off);
        }
        #pragma unroll
        for (int np = 0; np < 2; ++np) {
            const uint32_t off = (ks * 16 + krB) * 272 + (wn + np * 16 + ncB) * 2;
            uint32_t t[4];
            ldmBT(t, smb + SM_B(st, 0) + off);
            bhi[2*np][0] = t[0]; bhi[2*np][1] = t[1];
            bhi[2*np+1][0] = t[2]; bhi[2*np+1][1] = t[3];
            ldmBT(t, smb + SM_B(st, 1) + off);
            blo[2*np][0] = t[0]; blo[2*np][1] = t[1];
            blo[2*np+1][0] = t[2]; blo[2*np+1][1] = t[3];
        }
        #pragma unroll
        for (int m = 0; m < 4; ++m)
            #pragma unroll
            for (int n = 0; n < 4; ++n) {
                mma_bf16(acc[m][n], ahi[m], bhi[n]);
                mma_bf16(acc[m][n], ahi[m], blo[n]);
                mma_bf16(acc[m][n], alo[m], bhi[n]);
            }
    }
}

__device__ __forceinline__ void gemm_mainloop8(
    uint32_t smb, float acc[4][4][4],
    const __nv_bfloat16* gAhi, const __nv_bfloat16* gAlo,
    const __nv_bfloat16* gBhi, const __nv_bfloat16* gBlo,
    int m0, int n0, int tid, int wm, int wn, int lane)
{
    gemm_load_stage8(smb, 0, gAhi, gAlo, gBhi, gBlo, m0, n0, 0, tid);
    gemm_load_stage8(smb, 1, gAhi, gAlo, gBhi, gBlo, m0, n0, 32, tid);
    for (int s = 0; s < 32; ++s) {
        if (s < 31)
            asm volatile("cp.async.wait_group 1;" ::: "memory");
        else
            asm volatile("cp.async.wait_group 0;" ::: "memory");
        __syncthreads();
        if (s + 2 < 32)
            gemm_load_stage8(smb, (s + 2) % 3, gAhi, gAlo, gBhi, gBlo,
                             m0, n0, (s + 2) * 32, tid);
        gemm_compute_stage8(smb, s % 3, acc, wm, wn, lane);
    }
}

// ---------------------------------------------------------------------------
// QKV projection: writes bf16 hi/lo Q/K/V directly (Q scaled by 0.125)
// ---------------------------------------------------------------------------
__global__ __launch_bounds__(256, 2)
void gemm_qkv_bf16()
{
    extern __shared__ char sm[];
    const uint32_t smb = smem_u32(sm);
    const int tid = threadIdx.x, lane = tid & 31, warp = tid >> 5;
    const int wm = (warp >> 2) * 64, wn = (warp & 3) * 32;
    const int which = blockIdx.z;
    const int m0 = blockIdx.y * 128, n0 = blockIdx.x * 128;
    __nv_bfloat16* Ch = g_QKVbf[which][0];
    __nv_bfloat16* Cl = g_QKVbf[which][1];
    const float qs = (which == 0) ? 0.125f : 1.0f;

    float acc[4][4][4];
    #pragma unroll
    for (int m = 0; m < 4; ++m)
        #pragma unroll
        for (int n = 0; n < 4; ++n)
            #pragma unroll
            for (int e = 0; e < 4; ++e) acc[m][n][e] = 0.f;

    gemm_mainloop8(smb, acc, g_Abf[which][0], g_Abf[which][1],
                   g_Wbf[which][0], g_Wbf[which][1], m0, n0, tid, wm, wn, lane);

    #pragma unroll
    for (int m = 0; m < 4; ++m) {
        const int r0 = m0 + wm + m * 16 + (lane >> 2);
        #pragma unroll
        for (int n = 0; n < 4; ++n) {
            const int col = n0 + wn + n * 8 + (lane & 3) * 2;
            const int h = col >> 6, kc = col & 63;
            uint32_t hi, lo;
            {
                const int b = r0 >> 11, l = r0 & 2047;
                const size_t idx = (((size_t)(b * NHEADS + h) * SEQ) + l) * DK + kc;
                splitpair(acc[m][n][0] * qs, acc[m][n][1] * qs, hi, lo);
                *(uint32_t*)&Ch[idx] = hi;
                *(uint32_t*)&Cl[idx] = lo;
            }
            {
                const int r1 = r0 + 8;
                const int b = r1 >> 11, l = r1 & 2047;
                const size_t idx = (((size_t)(b * NHEADS + h) * SEQ) + l) * DK + kc;
                splitpair(acc[m][n][2] * qs, acc[m][n][3] * qs, hi, lo);
                *(uint32_t*)&Ch[idx] = hi;
                *(uint32_t*)&Cl[idx] = lo;
            }
        }
    }
}

// ---------------------------------------------------------------------------
// Output projection (validated stage8 core)
// ---------------------------------------------------------------------------
__global__ __launch_bounds__(256, 2)
void gemm_out_bf16(const float* __restrict__ out_b, float* __restrict__ out)
{
    extern __shared__ char sm[];
    const uint32_t smb = smem_u32(sm);
    const int tid = threadIdx.x, lane = tid & 31, warp = tid >> 5;
    const int wm = (warp >> 2) * 64, wn = (warp & 3) * 32;
    const int m0 = blockIdx.y * 128, n0 = blockIdx.x * 128;

    float acc[4][4][4];
    #pragma unroll
    for (int m = 0; m < 4; ++m)
        #pragma unroll
        for (int n = 0; n < 4; ++n)
            #pragma unroll
            for (int e = 0; e < 4; ++e) acc[m][n][e] = 0.f;

    gemm_mainloop8(smb, acc, g_Cbf[0], g_Cbf[1], g_Wobf[0], g_Wobf[1],
                   m0, n0, tid, wm, wn, lane);

    #pragma unroll
    for (int m = 0; m < 4; ++m) {
        const int r0 = m0 + wm + m * 16 + (lane >> 2);
        #pragma unroll
        for (int n = 0; n < 4; ++n) {
            const int col = n0 + wn + n * 8 + (lane & 3) * 2;
            const float b0 = out_b[col], b1 = out_b[col + 1];
            float2 v0 = { acc[m][n][0] + b0, acc[m][n][1] + b1 };
            float2 v1 = { acc[m][n][2] + b0, acc[m][n][3] + b1 };
            *(float2*)&out[(size_t)r0 * DMODEL + col] = v0;
            *(float2*)&out[(size_t)(r0 + 8) * DMODEL + col] = v1;
        }
    }
}

// ---------------------------------------------------------------------------
// Tensor-core flash attention.  CTA = 128 q-rows, 4 warps x 32 rows.
// NEW: scores use 2-term split (Qh*Kh + Qh*Kl; Ql dropped -> Q-lo never
// loaded, smem shrinks to Qhi + 2-stage KV ring = 92160 B).  Error budget:
// Q-hi rounding 2^-9 -> abs score err ~4.5e-4 -> rel_err ~4.5e-4 < 1e-3.
// P*V stays 3-term.  Phase bias cancels in softmax.
// ---------------------------------------------------------------------------
#define ATT_Q_BYTES 18432
#define ATT_SMEM (ATT_Q_BYTES + 2 * 36864)   // 92160

__device__ __forceinline__ void kv_load(
    uint32_t smb, int buf,
    const __nv_bfloat16* kh, const __nv_bfloat16* kl,
    const __nv_bfloat16* vh, const __nv_bfloat16* vl,
    int kt, int tid)
{
    const uint32_t base = smb + ATT_Q_BYTES + buf * 36864;
    const size_t goff = (size_t)kt * 64 * DK;
    #pragma unroll
    for (int j = 0; j < 16; ++j) {
        const int idx = tid + 128 * j;
        const int sel = idx >> 9, r = idx & 511;
        const int row = r >> 3, c16 = r & 7;
        const __nv_bfloat16* src =
            (sel == 0 ? kh : sel == 1 ? kl : sel == 2 ? vh : vl)
            + goff + row * DK + c16 * 8;
        CP16(base + sel * 9216 + row * 144 + c16 * 16, src);
    }
    CP_COMMIT();
}

__global__ __launch_bounds__(128)
void attn_mma_kernel()
{
    extern __shared__ char sm[];
    const uint32_t smb = smem_u32(sm);
    const int tid = threadIdx.x, lane = tid & 31, wid = tid >> 5;  // 0..3
    const int qt = blockIdx.x, bh = blockIdx.y;
    const size_t bhoff = (size_t)bh * SEQ * DK;

    const __nv_bfloat16* gQh = g_QKVbf[0][0] + bhoff + (size_t)qt * 128 * DK;
    const __nv_bfloat16* gKh = g_QKVbf[1][0] + bhoff;
    const __nv_bfloat16* gKl = g_QKVbf[1][1] + bhoff;
    const __nv_bfloat16* gVh = g_QKVbf[2][0] + bhoff;
    const __nv_bfloat16* gVl = g_QKVbf[2][1] + bhoff;

    // Q-hi tile load (group 0): 128 rows x 8 chunks = 1024
    #pragma unroll
    for (int j = 0; j < 8; ++j) {
        const int idx = tid + 128 * j;
        const int row = idx >> 3, c16 = idx & 7;
        CP16(smb + row * 144 + c16 * 16, gQh + row * DK + c16 * 8);
    }
    CP_COMMIT();
    kv_load(smb, 0, gKh, gKl, gVh, gVl, 0, tid);   // group 1

    asm volatile("cp.async.wait_group 1;" ::: "memory");  // Q ready
    __syncthreads();

    // Q-hi fragments (2 m-frags x 4 ks) held for the whole kernel
    uint32_t aQh[2][4][4];
    {
        const int rowA = (lane & 7) + ((lane >> 3) & 1) * 8;
        const int kcA  = (lane >> 4) * 8;
        #pragma unroll
        for (int mi = 0; mi < 2; ++mi)
            #pragma unroll
            for (int ks = 0; ks < 4; ++ks) {
                const uint32_t off =
                    (wid * 32 + mi * 16 + rowA) * 144 + (ks * 16 + kcA) * 2;
                ldmA(aQh[mi][ks], smb + off);
            }
    }

    float oc[2][8][4];
    #pragma unroll
    for (int mi = 0; mi < 2; ++mi)
        #pragma unroll
        for (int f = 0; f < 8; ++f)
            #pragma unroll
            for (int e = 0; e < 4; ++e) oc[mi][f][e] = 0.f;
    float mrow[2][2], lrow[2][2];
    #pragma unroll
    for (int mi = 0; mi < 2; ++mi) {
        mrow[mi][0] = -1e30f; mrow[mi][1] = -1e30f;
        lrow[mi][0] = 0.f;    lrow[mi][1] = 0.f;
    }

    const uint32_t krow  = (lane & 7) + ((lane >> 4) & 1) * 8;  // K b-frag rows
    const uint32_t kboff = ((lane >> 3) & 1) * 16;
    const int krB = (lane & 7) + ((lane >> 3) & 1) * 8;         // V b-frag rows
    const int ncB = (lane >> 4) * 8;

    for (int kt = 0; kt < 32; ++kt) {
        const int buf = kt & 1;
        if (kt < 31) {
            kv_load(smb, buf ^ 1, gKh, gKl, gVh, gVl, kt + 1, tid);
            asm volatile("cp.async.wait_group 1;" ::: "memory");
        } else {
            asm volatile("cp.async.wait_group 0;" ::: "memory");
        }
        __syncthreads();

        const uint32_t KH = smb + ATT_Q_BYTES + buf * 36864;
        const uint32_t KL = KH + 9216;
        const uint32_t VH = KH + 18432;
        const uint32_t VL = KH + 27648;

        // ---- S = Q K^T (2-term: Qh*Kh + Qh*Kl) ----
        float sc[2][8][4];
        #pragma unroll
        for (int mi = 0; mi < 2; ++mi)
            #pragma unroll
            for (int f = 0; f < 8; ++f)
                #pragma unroll
                for (int e = 0; e < 4; ++e) sc[mi][f][e] = 0.f;

        #pragma unroll
        for (int ks = 0; ks < 4; ++ks) {
            #pragma unroll
            for (int g = 0; g < 4; ++g) {
                uint32_t th[4], tl[4];
                const uint32_t off = (g * 16 + krow) * 144 + ks * 32 + kboff;
                ldmA(th, KH + off);
                ldmA(tl, KL + off);
                uint32_t b0h[2] = { th[0], th[1] }, b1h[2] = { th[2], th[3] };
                uint32_t b0l[2] = { tl[0], tl[1] }, b1l[2] = { tl[2], tl[3] };
                #pragma unroll
                for (int mi = 0; mi < 2; ++mi) {
                    mma_bf16(sc[mi][2*g],   aQh[mi][ks], b0h);
                    mma_bf16(sc[mi][2*g],   aQh[mi][ks], b0l);
                    mma_bf16(sc[mi][2*g+1], aQh[mi][ks], b1h);
                    mma_bf16(sc[mi][2*g+1], aQh[mi][ks], b1l);
                }
            }
        }

        // ---- online softmax + P pack, per m-frag ----
        uint32_t aPh[2][4][4], aPl[2][4][4];
        #pragma unroll
        for (int mi = 0; mi < 2; ++mi) {
            float mn0 = -1e30f, mn1 = -1e30f;
            #pragma unroll
            for (int f = 0; f < 8; ++f) {
                mn0 = fmaxf(mn0, fmaxf(sc[mi][f][0], sc[mi][f][1]));
                mn1 = fmaxf(mn1, fmaxf(sc[mi][f][2], sc[mi][f][3]));
            }
            mn0 = fmaxf(mn0, __shfl_xor_sync(0xffffffffu, mn0, 1));
            mn0 = fmaxf(mn0, __shfl_xor_sync(0xffffffffu, mn0, 2));
            mn1 = fmaxf(mn1, __shfl_xor_sync(0xffffffffu, mn1, 1));
            mn1 = fmaxf(mn1, __shfl_xor_sync(0xffffffffu, mn1, 2));
            const float M0 = fmaxf(mrow[mi][0], mn0);
            const float M1 = fmaxf(mrow[mi][1], mn1);
            const float c0 = __expf(mrow[mi][0] - M0);
            const float c1 = __expf(mrow[mi][1] - M1);
            float rs0 = 0.f, rs1 = 0.f;
            #pragma unroll
            for (int f = 0; f < 8; ++f) {
                sc[mi][f][0] = __expf(sc[mi][f][0] - M0); rs0 += sc[mi][f][0];
                sc[mi][f][1] = __expf(sc[mi][f][1] - M0); rs0 += sc[mi][f][1];
                sc[mi][f][2] = __expf(sc[mi][f][2] - M1); rs1 += sc[mi][f][2];
                sc[mi][f][3] = __expf(sc[mi][f][3] - M1); rs1 += sc[mi][f][3];
            }
            rs0 += __shfl_xor_sync(0xffffffffu, rs0, 1);
            rs0 += __shfl_xor_sync(0xffffffffu, rs0, 2);
            rs1 += __shfl_xor_sync(0xffffffffu, rs1, 1);
            rs1 += __shfl_xor_sync(0xffffffffu, rs1, 2);
            lrow[mi][0] = lrow[mi][0] * c0 + rs0;
            lrow[mi][1] = lrow[mi][1] * c1 + rs1;
            mrow[mi][0] = M0; mrow[mi][1] = M1;
            #pragma unroll
            for (int f = 0; f < 8; ++f) {
                oc[mi][f][0] *= c0; oc[mi][f][1] *= c0;
                oc[mi][f][2] *= c1; oc[mi][f][3] *= c1;
            }
            #pragma unroll
            for (int ks = 0; ks < 4; ++ks) {
                const int f0 = 2 * ks, f1 = 2 * ks + 1;
                splitpair(sc[mi][f0][0], sc[mi][f0][1], aPh[mi][ks][0], aPl[mi][ks][0]);
                splitpair(sc[mi][f0][2], sc[mi][f0][3], aPh[mi][ks][1], aPl[mi][ks][1]);
                splitpair(sc[mi][f1][0], sc[mi][f1][1], aPh[mi][ks][2], aPl[mi][ks][2]);
                splitpair(sc[mi][f1][2], sc[mi][f1][3], aPh[mi][ks][3], aPl[mi][ks][3]);
            }
        }

        // ---- O += P V (3-term split), 2 m-frags share each V fragment ----
        #pragma unroll
        for (int ks = 0; ks < 4; ++ks) {
            #pragma unroll
            for (int g = 0; g < 4; ++g) {
                uint32_t th[4], tl[4];
                const uint32_t off = (ks * 16 + krB) * 144 + (g * 16 + ncB) * 2;
                ldmBT(th, VH + off);
                ldmBT(tl, VL + off);
                uint32_t b0h[2] = { th[0], th[1] }, b1h[2] = { th[2], th[3] };
                uint32_t b0l[2] = { tl[0], tl[1] }, b1l[2] = { tl[2], tl[3] };
                #pragma unroll
                for (int mi = 0; mi < 2; ++mi) {
                    mma_bf16(oc[mi][2*g],   aPh[mi][ks], b0h);
                    mma_bf16(oc[mi][2*g],   aPh[mi][ks], b0l);
                    mma_bf16(oc[mi][2*g],   aPl[mi][ks], b0h);
                    mma_bf16(oc[mi][2*g+1], aPh[mi][ks], b1h);
                    mma_bf16(oc[mi][2*g+1], aPh[mi][ks], b1l);
                    mma_bf16(oc[mi][2*g+1], aPl[mi][ks], b1h);
                }
            }
        }
    }

    // ---- epilogue: normalize, split, write ctx bf16 hi/lo ----
    const int b = bh >> 4, h = bh & 15;
    #pragma unroll
    for (int mi = 0; mi < 2; ++mi) {
        const float i0 = 1.0f / lrow[mi][0], i1 = 1.0f / lrow[mi][1];
        const int lg0 = qt * 128 + wid * 32 + mi * 16 + (lane >> 2);
        const int lg1 = lg0 + 8;
        #pragma unroll
        for (int f = 0; f < 8; ++f) {
            const int col = h * 64 + 8 * f + (lane & 3) * 2;
            uint32_t hi, lo;
            splitpair(oc[mi][f][0] * i0, oc[mi][f][1] * i0, hi, lo);
            const size_t idx0 = ((size_t)(b * SEQ + lg0)) * DMODEL + col;
            *(uint32_t*)&g_Cbf[0][idx0] = hi;
            *(uint32_t*)&g_Cbf[1][idx0] = lo;
            splitpair(oc[mi][f][2] * i1, oc[mi][f][3] * i1, hi, lo);
            const size_t idx1 = ((size_t)(b * SEQ + lg1)) * DMODEL + col;
            *(uint32_t*)&g_Cbf[0][idx1] = hi;
            *(uint32_t*)&g_Cbf[1][idx1] = lo;
        }
    }
}

// ---------------------------------------------------------------------------
// Launch.  Inputs: query, key, value, Wq, Wk, Wv, out_w, out_b, coupling
// coupling is (correctly) unused: the Kuramoto phase bias is constant along
// the softmax axis and cancels exactly.
// ---------------------------------------------------------------------------
extern "C" void kernel_launch(void* const* d_in, const int* in_sizes, int n_in,
                              void* d_out, int out_size)
{
    const float* q     = (const float*)d_in[0];
    const float* k     = (const float*)d_in[1];
    const float* v     = (const float*)d_in[2];
    const float* wq    = (const float*)d_in[3];
    const float* wk    = (const float*)d_in[4];
    const float* wv    = (const float*)d_in[5];
    const float* out_w = (const float*)d_in[6];
    const float* out_b = (const float*)d_in[7];
    float* out = (float*)d_out;

    // merged bf16 hi/lo splits of all inputs (one launch, vectorized stores)
    convert_all_kernel<<<dim3(512, 7), 256>>>(q, k, v, wq, wk, wv, out_w);

    // QKV projection -> bf16 Q/K/V (validated 8-warp core)
    cudaFuncSetAttribute(gemm_qkv_bf16,
                         cudaFuncAttributeMaxDynamicSharedMemorySize, GSMEM);
    gemm_qkv_bf16<<<dim3(8, 32, 3), 256, GSMEM>>>();

    // tensor-core flash attention -> ctx bf16 hi/lo
    cudaFuncSetAttribute(attn_mma_kernel,
                         cudaFuncAttributeMaxDynamicSharedMemorySize, ATT_SMEM);
    attn_mma_kernel<<<dim3(SEQ / 128, BATCH * NHEADS), 128, ATT_SMEM>>>();

    // output projection (validated 8-warp core)
    cudaFuncSetAttribute(gemm_out_bf16,
                         cudaFuncAttributeMaxDynamicSharedMemorySize, GSMEM);
    gemm_out_bf16<<<dim3(8, 32), 256, GSMEM>>>(out_b, out);
}